// round 7
// baseline (speedup 1.0000x reference)
#include <cuda_runtime.h>
#include <cuda_bf16.h>
#include <math.h>
#include <stdint.h>

// Problem constants
#define Bb 4
#define Ss 2048
#define Dd 1024
#define Hh 4096
#define MM (Bb * Ss)   // 8192

// ---------------------------------------------------------------------------
// Device-global scratch (allocation-free rule)
// ---------------------------------------------------------------------------
__device__ __nv_bfloat16 g_xhi[(size_t)MM * Dd];
__device__ __nv_bfloat16 g_xlo[(size_t)MM * Dd];
__device__ __nv_bfloat16 g_w1hi[(size_t)Hh * Dd];
__device__ __nv_bfloat16 g_w1lo[(size_t)Hh * Dd];
__device__ __nv_bfloat16 g_w2hi[(size_t)Dd * Hh];
__device__ __nv_bfloat16 g_w2lo[(size_t)Dd * Hh];
__device__ __nv_bfloat16 g_hhi[(size_t)MM * Hh];
__device__ __nv_bfloat16 g_hlo[(size_t)MM * Hh];
__device__ float g_U1[MM * 4];
__device__ float g_V[MM * 16];

__device__ __forceinline__ float gelu_exact(float v) {
    return 0.5f * v * (1.0f + erff(v * 0.70710678118654752f));
}

__device__ __forceinline__ uint32_t smem_u32(const void* p) {
    uint32_t a;
    asm("{ .reg .u64 t; cvta.to.shared.u64 t, %1; cvt.u32.u64 %0, t; }"
        : "=r"(a) : "l"(p));
    return a;
}

// ---------------------------------------------------------------------------
// mma / ldmatrix / cp.async primitives (baseline sm_80+ PTX -> sm_103 OK)
// ---------------------------------------------------------------------------
__device__ __forceinline__ void mma16816(float* d, const uint32_t* a, const uint32_t* b) {
    asm volatile(
        "mma.sync.aligned.m16n8k16.row.col.f32.bf16.bf16.f32 "
        "{%0,%1,%2,%3}, {%4,%5,%6,%7}, {%8,%9}, {%0,%1,%2,%3};"
        : "+f"(d[0]), "+f"(d[1]), "+f"(d[2]), "+f"(d[3])
        : "r"(a[0]), "r"(a[1]), "r"(a[2]), "r"(a[3]), "r"(b[0]), "r"(b[1]));
}

__device__ __forceinline__ void ldm4(uint32_t* r, uint32_t addr) {
    asm volatile("ldmatrix.sync.aligned.m8n8.x4.shared.b16 {%0,%1,%2,%3}, [%4];"
                 : "=r"(r[0]), "=r"(r[1]), "=r"(r[2]), "=r"(r[3]) : "r"(addr));
}

__device__ __forceinline__ void cp16(uint32_t s, const void* g) {
    asm volatile("cp.async.cg.shared.global [%0], [%1], 16;" :: "r"(s), "l"(g));
}
__device__ __forceinline__ void cp_commit() {
    asm volatile("cp.async.commit_group;" ::: "memory");
}
template <int N>
__device__ __forceinline__ void cp_wait() {
    asm volatile("cp.async.wait_group %0;" :: "n"(N) : "memory");
}

// ---------------------------------------------------------------------------
// Tiling constants: BK=16, 4-stage cp.async ring
// ---------------------------------------------------------------------------
#define BK 16
#define TSTRIDE 48                    // 16 bf16 = 32B data + 16B pad (16B-aligned rows)
#define TILE_B (128 * TSTRIDE)        // 6144 B per tile
#define BUF_B (4 * TILE_B)            // Ahi, Alo, Bhi, Blo = 24576 B per stage
#define NSTAGE 4
#define SMEM_TOTAL (NSTAGE * BUF_B)   // 98304 B

extern __shared__ char dsmem[];

// Issue cp.async loads for one BK-chunk into one stage. 4 cp16 per thread.
__device__ __forceinline__ void issue_chunk(
    uint32_t sbuf,
    const __nv_bfloat16* __restrict__ Ahi, const __nv_bfloat16* __restrict__ Alo,
    const __nv_bfloat16* __restrict__ Bhi, const __nv_bfloat16* __restrict__ Blo,
    int m0, int n0, int kc, int KDIM, int tid)
{
    int row = tid >> 1, c16 = tid & 1;
    uint32_t soff = (uint32_t)(row * TSTRIDE + c16 * 16);
    size_t ga = (size_t)(m0 + row) * KDIM + kc * BK + c16 * 8;
    size_t gb = (size_t)(n0 + row) * KDIM + kc * BK + c16 * 8;
    cp16(sbuf + 0 * TILE_B + soff, Ahi + ga);
    cp16(sbuf + 1 * TILE_B + soff, Alo + ga);
    cp16(sbuf + 2 * TILE_B + soff, Bhi + gb);
    cp16(sbuf + 3 * TILE_B + soff, Blo + gb);
}

// Load 4 A fragments (64 rows x k16) from a tile.
__device__ __forceinline__ void lda(uint32_t a[4][4], uint32_t tile, int wm, int lane) {
    uint32_t koff = (uint32_t)((lane >> 4) * 16);
    #pragma unroll
    for (int mi = 0; mi < 4; mi++) {
        uint32_t addr = tile + (uint32_t)((wm * 64 + mi * 16 + (lane & 15)) * TSTRIDE) + koff;
        ldm4(a[mi], addr);
    }
}

// Load 4 B fragments (32 cols x k16) from a tile.
__device__ __forceinline__ void ldb(uint32_t b[4][2], uint32_t tile, int wn, int lane) {
    #pragma unroll
    for (int g = 0; g < 2; g++) {
        int nrow = wn * 32 + g * 16 + (lane & 7) + ((lane >> 4) & 1) * 8;
        uint32_t addr = tile + (uint32_t)(nrow * TSTRIDE) +
                        (uint32_t)(((lane >> 3) & 1) * 16);
        uint32_t r[4];
        ldm4(r, addr);
        b[2 * g][0] = r[0]; b[2 * g][1] = r[1];
        b[2 * g + 1][0] = r[2]; b[2 * g + 1][1] = r[3];
    }
}

__device__ __forceinline__ void mma_set(float acc[4][4][4], uint32_t a[4][4], uint32_t b[4][2]) {
    #pragma unroll
    for (int mi = 0; mi < 4; mi++)
        #pragma unroll
        for (int ni = 0; ni < 4; ni++)
            mma16816(acc[mi][ni], a[mi], b[ni]);
}

// Split-bf16 3-term compute on one staged BK=16 chunk: 12 LDSM + 48 MMA.
__device__ __forceinline__ void compute_chunk(uint32_t sbuf, int wm, int wn, int lane,
                                              float acc[4][4][4]) {
    uint32_t a[4][4], b_hi[4][2], b_lo[4][2];
    lda(a, sbuf + 0 * TILE_B, wm, lane);     // Ahi
    ldb(b_hi, sbuf + 2 * TILE_B, wn, lane);
    mma_set(acc, a, b_hi);                   // Ahi * Bhi
    ldb(b_lo, sbuf + 3 * TILE_B, wn, lane);
    mma_set(acc, a, b_lo);                   // Ahi * Blo
    lda(a, sbuf + 1 * TILE_B, wm, lane);     // Alo (overwrite)
    mma_set(acc, a, b_hi);                   // Alo * Bhi
}

// Full mainloop: 4-stage ring, 3 chunks of prefetch, ONE barrier per chunk.
template <int KDIM>
__device__ __forceinline__ void gemm_mma(
    const __nv_bfloat16* __restrict__ Ahi, const __nv_bfloat16* __restrict__ Alo,
    const __nv_bfloat16* __restrict__ Bhi, const __nv_bfloat16* __restrict__ Blo,
    int m0, int n0, float acc[4][4][4])
{
    int tid = threadIdx.x;
    int lane = tid & 31, wid = tid >> 5;
    int wm = wid >> 2, wn = wid & 3;
    uint32_t sbase = smem_u32(dsmem);

    #pragma unroll
    for (int mi = 0; mi < 4; mi++)
        #pragma unroll
        for (int ni = 0; ni < 4; ni++)
            #pragma unroll
            for (int q = 0; q < 4; q++) acc[mi][ni][q] = 0.f;

    const int NC = KDIM / BK;
    #pragma unroll
    for (int p = 0; p < NSTAGE - 1; p++) {
        issue_chunk(sbase + p * BUF_B, Ahi, Alo, Bhi, Blo, m0, n0, p, KDIM, tid);
        cp_commit();
    }
    for (int c = 0; c < NC; c++) {
        // Barrier first: all warps must be done reading stage (c+3)%4 (used at
        // iteration c-1) before it is overwritten below.
        __syncthreads();
        if (c + NSTAGE - 1 < NC) {
            issue_chunk(sbase + ((c + NSTAGE - 1) & 3) * BUF_B, Ahi, Alo, Bhi, Blo,
                        m0, n0, c + NSTAGE - 1, KDIM, tid);
            cp_commit();
            cp_wait<NSTAGE - 1>();           // stage c complete (3 newer pending)
        } else {
            int rem = NC - 1 - c;            // pending groups after this point
            if (rem >= 3)      cp_wait<3>();
            else if (rem == 2) cp_wait<2>();
            else if (rem == 1) cp_wait<1>();
            else               cp_wait<0>();
        }
        compute_chunk(sbase + (c & 3) * BUF_B, wm, wn, lane, acc);
    }
}

// ---------------------------------------------------------------------------
// cvt: fp32 -> (hi, lo) bf16 split
// ---------------------------------------------------------------------------
__global__ void cvt_kernel(const float* __restrict__ src,
                           __nv_bfloat16* __restrict__ hi,
                           __nv_bfloat16* __restrict__ lo, int n4) {
    int i = blockIdx.x * blockDim.x + threadIdx.x;
    if (i >= n4) return;
    float4 v = ((const float4*)src)[i];
    __nv_bfloat16 h0 = __float2bfloat16(v.x), h1 = __float2bfloat16(v.y);
    __nv_bfloat16 h2 = __float2bfloat16(v.z), h3 = __float2bfloat16(v.w);
    __nv_bfloat16 l0 = __float2bfloat16(v.x - __bfloat162float(h0));
    __nv_bfloat16 l1 = __float2bfloat16(v.y - __bfloat162float(h1));
    __nv_bfloat16 l2 = __float2bfloat16(v.z - __bfloat162float(h2));
    __nv_bfloat16 l3 = __float2bfloat16(v.w - __bfloat162float(h3));
    ((__nv_bfloat162*)hi)[2 * i]     = __halves2bfloat162(h0, h1);
    ((__nv_bfloat162*)hi)[2 * i + 1] = __halves2bfloat162(h2, h3);
    ((__nv_bfloat162*)lo)[2 * i]     = __halves2bfloat162(l0, l1);
    ((__nv_bfloat162*)lo)[2 * i + 1] = __halves2bfloat162(l2, l3);
}

// ---------------------------------------------------------------------------
// U1[b,s,r] = x[b,s,:] . x[b, 2+2r, :]  (fp32 exact); 1 warp/(b,s)
// ---------------------------------------------------------------------------
__global__ void u1_kernel(const float* __restrict__ x) {
    int gw = (blockIdx.x * blockDim.x + threadIdx.x) >> 5;
    int lane = threadIdx.x & 31;
    if (gw >= MM) return;
    int b = gw >> 11;
    const float4* xr = (const float4*)(x + (size_t)gw * Dd);
    const float4* o0 = (const float4*)(x + ((size_t)b * Ss + 2) * Dd);
    const float4* o1 = (const float4*)(x + ((size_t)b * Ss + 4) * Dd);
    const float4* o2 = (const float4*)(x + ((size_t)b * Ss + 6) * Dd);
    const float4* o3 = (const float4*)(x + ((size_t)b * Ss + 8) * Dd);
    float a0 = 0.f, a1 = 0.f, a2 = 0.f, a3 = 0.f;
    for (int j = lane; j < Dd / 4; j += 32) {
        float4 xv = xr[j];
        float4 v;
        v = o0[j]; a0 += xv.x * v.x + xv.y * v.y + xv.z * v.z + xv.w * v.w;
        v = o1[j]; a1 += xv.x * v.x + xv.y * v.y + xv.z * v.z + xv.w * v.w;
        v = o2[j]; a2 += xv.x * v.x + xv.y * v.y + xv.z * v.z + xv.w * v.w;
        v = o3[j]; a3 += xv.x * v.x + xv.y * v.y + xv.z * v.z + xv.w * v.w;
    }
    #pragma unroll
    for (int off = 16; off; off >>= 1) {
        a0 += __shfl_xor_sync(0xFFFFFFFFu, a0, off);
        a1 += __shfl_xor_sync(0xFFFFFFFFu, a1, off);
        a2 += __shfl_xor_sync(0xFFFFFFFFu, a2, off);
        a3 += __shfl_xor_sync(0xFFFFFFFFu, a3, off);
    }
    if (lane == 0) {
        g_U1[gw * 4 + 0] = a0;
        g_U1[gw * 4 + 1] = a1;
        g_U1[gw * 4 + 2] = a2;
        g_U1[gw * 4 + 3] = a3;
    }
}

// ---------------------------------------------------------------------------
// V[b,s,r,k] = sum_j h[b,s,k*1024+j] * x[b,10+2r,j]; h = hhi + hlo
// ---------------------------------------------------------------------------
__global__ void v_kernel(const float* __restrict__ x) {
    int gw = (blockIdx.x * blockDim.x + threadIdx.x) >> 5;
    int lane = threadIdx.x & 31;
    if (gw >= MM) return;
    int b = gw >> 11;
    const float2* od[4];
    #pragma unroll
    for (int r = 0; r < 4; r++)
        od[r] = (const float2*)(x + ((size_t)b * Ss + 10 + 2 * r) * Dd);
    float acc[16];
    #pragma unroll
    for (int i = 0; i < 16; i++) acc[i] = 0.f;
    #pragma unroll
    for (int k = 0; k < 4; k++) {
        const __nv_bfloat162* hh = (const __nv_bfloat162*)(g_hhi + (size_t)gw * Hh + k * 1024);
        const __nv_bfloat162* hl = (const __nv_bfloat162*)(g_hlo + (size_t)gw * Hh + k * 1024);
        for (int j = lane; j < 512; j += 32) {
            float2 a = __bfloat1622float2(hh[j]);
            float2 c = __bfloat1622float2(hl[j]);
            float hx = a.x + c.x, hy = a.y + c.y;
            #pragma unroll
            for (int r = 0; r < 4; r++) {
                float2 ov = od[r][j];
                acc[r * 4 + k] += hx * ov.x + hy * ov.y;
            }
        }
    }
    #pragma unroll
    for (int i = 0; i < 16; i++) {
        #pragma unroll
        for (int off = 16; off; off >>= 1)
            acc[i] += __shfl_xor_sync(0xFFFFFFFFu, acc[i], off);
    }
    if (lane == 0) {
        #pragma unroll
        for (int i = 0; i < 16; i++) g_V[gw * 16 + i] = acc[i];
    }
}

// ---------------------------------------------------------------------------
// GEMM1: h = gelu(x@W1^T + scale*lora1 + b1) -> split-bf16 g_hhi/g_hlo
// ---------------------------------------------------------------------------
__global__ __launch_bounds__(256, 2)
void gemm1_mma(const float* __restrict__ x, const float* __restrict__ b1,
               const float* __restrict__ scale_p) {
    int m0 = blockIdx.y * 128, n0 = blockIdx.x * 128;
    float acc[4][4][4];
    gemm_mma<Dd>(g_xhi, g_xlo, g_w1hi, g_w1lo, m0, n0, acc);

    int lane = threadIdx.x & 31, wid = threadIdx.x >> 5;
    int wm = wid >> 2, wn = wid & 3;
    float sc = *scale_p;
    int r = n0 >> 10;
    #pragma unroll
    for (int mi = 0; mi < 4; mi++) {
        #pragma unroll
        for (int half = 0; half < 2; half++) {
            int m = m0 + wm * 64 + mi * 16 + (lane >> 2) + half * 8;
            int b = m >> 11;
            float u = sc * g_U1[m * 4 + r];
            const float* ev = x + ((size_t)b * Ss + 1 + 2 * r) * Dd;
            #pragma unroll
            for (int ni = 0; ni < 4; ni++) {
                int n = n0 + wn * 32 + ni * 8 + 2 * (lane & 3);
                int nc = n & 1023;
                float c0 = acc[mi][ni][half * 2 + 0] + u * ev[nc]     + b1[n];
                float c1 = acc[mi][ni][half * 2 + 1] + u * ev[nc + 1] + b1[n + 1];
                float gg0 = gelu_exact(c0), gg1 = gelu_exact(c1);
                __nv_bfloat16 h0 = __float2bfloat16(gg0);
                __nv_bfloat16 h1 = __float2bfloat16(gg1);
                __nv_bfloat16 l0 = __float2bfloat16(gg0 - __bfloat162float(h0));
                __nv_bfloat16 l1 = __float2bfloat16(gg1 - __bfloat162float(h1));
                *(__nv_bfloat162*)(g_hhi + (size_t)m * Hh + n) = __halves2bfloat162(h0, h1);
                *(__nv_bfloat162*)(g_hlo + (size_t)m * Hh + n) = __halves2bfloat162(l0, l1);
            }
        }
    }
}

// ---------------------------------------------------------------------------
// GEMM2: out = h@W2^T + scale*lora2 + b2  (fp32 out)
// ---------------------------------------------------------------------------
__global__ __launch_bounds__(256, 2)
void gemm2_mma(const float* __restrict__ x, const float* __restrict__ b2,
               const float* __restrict__ scale_p, float* __restrict__ out) {
    int m0 = blockIdx.y * 128, n0 = blockIdx.x * 128;
    float acc[4][4][4];
    gemm_mma<Hh>(g_hhi, g_hlo, g_w2hi, g_w2lo, m0, n0, acc);

    int lane = threadIdx.x & 31, wid = threadIdx.x >> 5;
    int wm = wid >> 2, wn = wid & 3;
    float sc = *scale_p;
    int r = n0 >> 8;
    #pragma unroll
    for (int mi = 0; mi < 4; mi++) {
        #pragma unroll
        for (int half = 0; half < 2; half++) {
            int m = m0 + wm * 64 + mi * 16 + (lane >> 2) + half * 8;
            int b = m >> 11;
            float4 vv = *(const float4*)&g_V[m * 16 + r * 4];
            const float4* ev2 = (const float4*)(x + ((size_t)b * Ss + 9 + 2 * r) * Dd);
            #pragma unroll
            for (int ni = 0; ni < 4; ni++) {
                int n = n0 + wn * 32 + ni * 8 + 2 * (lane & 3);
                float4 e0 = ev2[n & 255];
                float4 e1 = ev2[(n + 1) & 255];
                float lora0 = vv.x * e0.x + vv.y * e0.y + vv.z * e0.z + vv.w * e0.w;
                float lora1 = vv.x * e1.x + vv.y * e1.y + vv.z * e1.z + vv.w * e1.w;
                float2 o;
                o.x = acc[mi][ni][half * 2 + 0] + sc * lora0 + b2[n];
                o.y = acc[mi][ni][half * 2 + 1] + sc * lora1 + b2[n + 1];
                *(float2*)(out + (size_t)m * Dd + n) = o;
            }
        }
    }
}

// ---------------------------------------------------------------------------
extern "C" void kernel_launch(void* const* d_in, const int* in_sizes, int n_in,
                              void* d_out, int out_size) {
    const float* x     = (const float*)d_in[0];
    const float* W1    = (const float*)d_in[1];
    const float* b1    = (const float*)d_in[2];
    const float* W2    = (const float*)d_in[3];
    const float* b2    = (const float*)d_in[4];
    const float* scale = (const float*)d_in[5];
    float* out = (float*)d_out;

    cudaFuncSetAttribute(gemm1_mma, cudaFuncAttributeMaxDynamicSharedMemorySize, SMEM_TOTAL);
    cudaFuncSetAttribute(gemm2_mma, cudaFuncAttributeMaxDynamicSharedMemorySize, SMEM_TOTAL);

    __nv_bfloat16 *xhi, *xlo, *w1hi, *w1lo, *w2hi, *w2lo;
    cudaGetSymbolAddress((void**)&xhi, g_xhi);
    cudaGetSymbolAddress((void**)&xlo, g_xlo);
    cudaGetSymbolAddress((void**)&w1hi, g_w1hi);
    cudaGetSymbolAddress((void**)&w1lo, g_w1lo);
    cudaGetSymbolAddress((void**)&w2hi, g_w2hi);
    cudaGetSymbolAddress((void**)&w2lo, g_w2lo);

    u1_kernel<<<MM / 8, 256>>>(x);

    cvt_kernel<<<(MM * Dd / 4 + 255) / 256, 256>>>(x, xhi, xlo, MM * Dd / 4);
    cvt_kernel<<<(Hh * Dd / 4 + 255) / 256, 256>>>(W1, w1hi, w1lo, Hh * Dd / 4);
    cvt_kernel<<<(Dd * Hh / 4 + 255) / 256, 256>>>(W2, w2hi, w2lo, Dd * Hh / 4);

    dim3 g1(Hh / 128, MM / 128);   // (32, 64)
    gemm1_mma<<<g1, 256, SMEM_TOTAL>>>(x, b1, scale);

    v_kernel<<<MM / 8, 256>>>(x);

    dim3 g2(Dd / 128, MM / 128);   // (8, 64)
    gemm2_mma<<<g2, 256, SMEM_TOTAL>>>(x, b2, scale, out);
}

// round 8
// speedup vs baseline: 1.1314x; 1.1314x over previous
#include <cuda_runtime.h>
#include <cuda_bf16.h>
#include <math.h>
#include <stdint.h>

// Problem constants
#define Bb 4
#define Ss 2048
#define Dd 1024
#define Hh 4096
#define MM (Bb * Ss)   // 8192

// ---------------------------------------------------------------------------
// Device-global scratch (allocation-free rule)
// ---------------------------------------------------------------------------
__device__ __nv_bfloat16 g_xhi[(size_t)MM * Dd];
__device__ __nv_bfloat16 g_xlo[(size_t)MM * Dd];
__device__ __nv_bfloat16 g_w1hi[(size_t)Hh * Dd];
__device__ __nv_bfloat16 g_w1lo[(size_t)Hh * Dd];
__device__ __nv_bfloat16 g_w2hi[(size_t)Dd * Hh];
__device__ __nv_bfloat16 g_w2lo[(size_t)Dd * Hh];
__device__ __nv_bfloat16 g_hhi[(size_t)MM * Hh];
__device__ __nv_bfloat16 g_hlo[(size_t)MM * Hh];
__device__ float g_U1[MM * 4];
__device__ float g_V[MM * 16];

__device__ __forceinline__ float gelu_exact(float v) {
    return 0.5f * v * (1.0f + erff(v * 0.70710678118654752f));
}

__device__ __forceinline__ uint32_t smem_u32(const void* p) {
    uint32_t a;
    asm("{ .reg .u64 t; cvta.to.shared.u64 t, %1; cvt.u32.u64 %0, t; }"
        : "=r"(a) : "l"(p));
    return a;
}

// ---------------------------------------------------------------------------
// mma / ldmatrix / cp.async primitives (baseline sm_80+ PTX -> sm_103 OK)
// ---------------------------------------------------------------------------
__device__ __forceinline__ void mma16816(float* d, const uint32_t* a, const uint32_t* b) {
    asm volatile(
        "mma.sync.aligned.m16n8k16.row.col.f32.bf16.bf16.f32 "
        "{%0,%1,%2,%3}, {%4,%5,%6,%7}, {%8,%9}, {%0,%1,%2,%3};"
        : "+f"(d[0]), "+f"(d[1]), "+f"(d[2]), "+f"(d[3])
        : "r"(a[0]), "r"(a[1]), "r"(a[2]), "r"(a[3]), "r"(b[0]), "r"(b[1]));
}

__device__ __forceinline__ void ldm4(uint32_t* r, uint32_t addr) {
    asm volatile("ldmatrix.sync.aligned.m8n8.x4.shared.b16 {%0,%1,%2,%3}, [%4];"
                 : "=r"(r[0]), "=r"(r[1]), "=r"(r[2]), "=r"(r[3]) : "r"(addr));
}

__device__ __forceinline__ void cp16(uint32_t s, const void* g) {
    asm volatile("cp.async.cg.shared.global [%0], [%1], 16;" :: "r"(s), "l"(g));
}
__device__ __forceinline__ void cp_commit() {
    asm volatile("cp.async.commit_group;" ::: "memory");
}
__device__ __forceinline__ void cp_wait0() {
    asm volatile("cp.async.wait_group 0;" ::: "memory");
}
__device__ __forceinline__ void cp_wait1() {
    asm volatile("cp.async.wait_group 1;" ::: "memory");
}

// ---------------------------------------------------------------------------
// Tiling constants (R6-proven): BK=32, double buffer
// ---------------------------------------------------------------------------
#define BK 32
#define TSTRIDE 80                    // 32 bf16 = 64B data + 16B pad

// gemm1: 128x128 tiles
#define TILE_B (128 * TSTRIDE)        // 10240 B per tile
#define BUF_B (4 * TILE_B)            // Ahi, Alo, Bhi, Blo
#define SMEM_TOTAL (2 * BUF_B)        // 81920 B

// gemm2: 64x128 tiles (BM=64) -> 1024 CTAs, kills wave quantization
#define TILE_A2 (64 * TSTRIDE)        // 5120
#define TILE_B2 (128 * TSTRIDE)       // 10240
#define BUF2 (2 * TILE_A2 + 2 * TILE_B2)  // 30720: [Ahi][Alo][Bhi][Blo]
#define SMEM2 (2 * BUF2)              // 61440

extern __shared__ char dsmem[];

// ===========================================================================
// gemm1 core (exact R6): 128x128, 8 warps of 64x32
// ===========================================================================
__device__ __forceinline__ void issue_chunk(
    uint32_t sbuf,
    const __nv_bfloat16* __restrict__ Ahi, const __nv_bfloat16* __restrict__ Alo,
    const __nv_bfloat16* __restrict__ Bhi, const __nv_bfloat16* __restrict__ Blo,
    int m0, int n0, int kc, int KDIM, int tid)
{
    #pragma unroll
    for (int i = 0; i < 2; i++) {
        int idx = tid + i * 256;
        int row = idx >> 2, c4 = idx & 3;
        uint32_t soff = (uint32_t)(row * TSTRIDE + c4 * 16);
        size_t ga = (size_t)(m0 + row) * KDIM + kc * BK + c4 * 8;
        size_t gb = (size_t)(n0 + row) * KDIM + kc * BK + c4 * 8;
        cp16(sbuf + 0 * TILE_B + soff, Ahi + ga);
        cp16(sbuf + 1 * TILE_B + soff, Alo + ga);
        cp16(sbuf + 2 * TILE_B + soff, Bhi + gb);
        cp16(sbuf + 3 * TILE_B + soff, Blo + gb);
    }
}

__device__ __forceinline__ void lda(uint32_t a[4][4], uint32_t tile, int wm, int lane, int ks) {
    uint32_t koff = (uint32_t)(ks * 32 + (lane >> 4) * 16);
    #pragma unroll
    for (int mi = 0; mi < 4; mi++) {
        uint32_t addr = tile + (uint32_t)((wm * 64 + mi * 16 + (lane & 15)) * TSTRIDE) + koff;
        ldm4(a[mi], addr);
    }
}

__device__ __forceinline__ void ldb(uint32_t b[4][2], uint32_t tile, int wn, int lane, int ks) {
    #pragma unroll
    for (int g = 0; g < 2; g++) {
        int nrow = wn * 32 + g * 16 + (lane & 7) + ((lane >> 4) & 1) * 8;
        uint32_t addr = tile + (uint32_t)(nrow * TSTRIDE) +
                        (uint32_t)(ks * 32 + ((lane >> 3) & 1) * 16);
        uint32_t r[4];
        ldm4(r, addr);
        b[2 * g][0] = r[0]; b[2 * g][1] = r[1];
        b[2 * g + 1][0] = r[2]; b[2 * g + 1][1] = r[3];
    }
}

__device__ __forceinline__ void mma_set(float acc[4][4][4], uint32_t a[4][4], uint32_t b[4][2]) {
    #pragma unroll
    for (int mi = 0; mi < 4; mi++)
        #pragma unroll
        for (int ni = 0; ni < 4; ni++)
            mma16816(acc[mi][ni], a[mi], b[ni]);
}

__device__ __forceinline__ void compute_chunk(uint32_t sbuf, int wm, int wn, int lane,
                                              float acc[4][4][4]) {
    #pragma unroll
    for (int ks = 0; ks < 2; ks++) {
        uint32_t a[4][4], b_hi[4][2], b_lo[4][2];
        lda(a, sbuf + 0 * TILE_B, wm, lane, ks);   // Ahi
        ldb(b_hi, sbuf + 2 * TILE_B, wn, lane, ks);
        mma_set(acc, a, b_hi);                     // Ahi * Bhi
        ldb(b_lo, sbuf + 3 * TILE_B, wn, lane, ks);
        mma_set(acc, a, b_lo);                     // Ahi * Blo
        lda(a, sbuf + 1 * TILE_B, wm, lane, ks);   // Alo (overwrite)
        mma_set(acc, a, b_hi);                     // Alo * Bhi
    }
}

template <int KDIM>
__device__ __forceinline__ void gemm_mma(
    const __nv_bfloat16* __restrict__ Ahi, const __nv_bfloat16* __restrict__ Alo,
    const __nv_bfloat16* __restrict__ Bhi, const __nv_bfloat16* __restrict__ Blo,
    int m0, int n0, float acc[4][4][4])
{
    int tid = threadIdx.x;
    int lane = tid & 31, wid = tid >> 5;
    int wm = wid >> 2, wn = wid & 3;
    uint32_t sbase = smem_u32(dsmem);

    #pragma unroll
    for (int mi = 0; mi < 4; mi++)
        #pragma unroll
        for (int ni = 0; ni < 4; ni++)
            #pragma unroll
            for (int q = 0; q < 4; q++) acc[mi][ni][q] = 0.f;

    const int NC = KDIM / BK;
    issue_chunk(sbase, Ahi, Alo, Bhi, Blo, m0, n0, 0, KDIM, tid);
    cp_commit();
    for (int c = 0; c < NC; c++) {
        if (c + 1 < NC) {
            issue_chunk(sbase + ((c + 1) & 1) * BUF_B, Ahi, Alo, Bhi, Blo,
                        m0, n0, c + 1, KDIM, tid);
            cp_commit();
            cp_wait1();
        } else {
            cp_wait0();
        }
        __syncthreads();
        compute_chunk(sbase + (c & 1) * BUF_B, wm, wn, lane, acc);
        __syncthreads();
    }
}

// ===========================================================================
// gemm2 core: 64x128, 8 warps as 2(M) x 4(N) of 32x32 warp tiles
// ===========================================================================
__device__ __forceinline__ void issue_chunk2(
    uint32_t sbuf,
    const __nv_bfloat16* __restrict__ Ahi, const __nv_bfloat16* __restrict__ Alo,
    const __nv_bfloat16* __restrict__ Bhi, const __nv_bfloat16* __restrict__ Blo,
    int m0, int n0, int kc, int KDIM, int tid)
{
    {   // A: 64 rows x 4 quads = 256 slots = 1 per thread
        int row = tid >> 2, c4 = tid & 3;
        uint32_t soff = (uint32_t)(row * TSTRIDE + c4 * 16);
        size_t ga = (size_t)(m0 + row) * KDIM + kc * BK + c4 * 8;
        cp16(sbuf + 0 * TILE_A2 + soff, Ahi + ga);
        cp16(sbuf + 1 * TILE_A2 + soff, Alo + ga);
    }
    #pragma unroll
    for (int i = 0; i < 2; i++) {  // B: 128 rows x 4 quads = 512 slots
        int idx = tid + i * 256;
        int row = idx >> 2, c4 = idx & 3;
        uint32_t soff = (uint32_t)(row * TSTRIDE + c4 * 16);
        size_t gb = (size_t)(n0 + row) * KDIM + kc * BK + c4 * 8;
        cp16(sbuf + 2 * TILE_A2 + 0 * TILE_B2 + soff, Bhi + gb);
        cp16(sbuf + 2 * TILE_A2 + 1 * TILE_B2 + soff, Blo + gb);
    }
}

__device__ __forceinline__ void lda2(uint32_t a[2][4], uint32_t tile, int wm, int lane, int ks) {
    uint32_t koff = (uint32_t)(ks * 32 + (lane >> 4) * 16);
    #pragma unroll
    for (int mi = 0; mi < 2; mi++) {
        uint32_t addr = tile + (uint32_t)((wm * 32 + mi * 16 + (lane & 15)) * TSTRIDE) + koff;
        ldm4(a[mi], addr);
    }
}

__device__ __forceinline__ void mma_set2(float acc[2][4][4], uint32_t a[2][4], uint32_t b[4][2]) {
    #pragma unroll
    for (int mi = 0; mi < 2; mi++)
        #pragma unroll
        for (int ni = 0; ni < 4; ni++)
            mma16816(acc[mi][ni], a[mi], b[ni]);
}

__device__ __forceinline__ void compute_chunk2(uint32_t sbuf, int wm, int wn, int lane,
                                               float acc[2][4][4]) {
    uint32_t btile = sbuf + 2 * TILE_A2;
    #pragma unroll
    for (int ks = 0; ks < 2; ks++) {
        uint32_t a[2][4], b_hi[4][2], b_lo[4][2];
        lda2(a, sbuf + 0 * TILE_A2, wm, lane, ks);   // Ahi
        ldb(b_hi, btile + 0 * TILE_B2, wn, lane, ks);
        mma_set2(acc, a, b_hi);                      // Ahi * Bhi
        ldb(b_lo, btile + 1 * TILE_B2, wn, lane, ks);
        mma_set2(acc, a, b_lo);                      // Ahi * Blo
        lda2(a, sbuf + 1 * TILE_A2, wm, lane, ks);   // Alo
        mma_set2(acc, a, b_hi);                      // Alo * Bhi
    }
}

template <int KDIM>
__device__ __forceinline__ void gemm_mma2(
    const __nv_bfloat16* __restrict__ Ahi, const __nv_bfloat16* __restrict__ Alo,
    const __nv_bfloat16* __restrict__ Bhi, const __nv_bfloat16* __restrict__ Blo,
    int m0, int n0, float acc[2][4][4])
{
    int tid = threadIdx.x;
    int lane = tid & 31, wid = tid >> 5;
    int wm = wid >> 2, wn = wid & 3;
    uint32_t sbase = smem_u32(dsmem);

    #pragma unroll
    for (int mi = 0; mi < 2; mi++)
        #pragma unroll
        for (int ni = 0; ni < 4; ni++)
            #pragma unroll
            for (int q = 0; q < 4; q++) acc[mi][ni][q] = 0.f;

    const int NC = KDIM / BK;
    issue_chunk2(sbase, Ahi, Alo, Bhi, Blo, m0, n0, 0, KDIM, tid);
    cp_commit();
    for (int c = 0; c < NC; c++) {
        if (c + 1 < NC) {
            issue_chunk2(sbase + ((c + 1) & 1) * BUF2, Ahi, Alo, Bhi, Blo,
                         m0, n0, c + 1, KDIM, tid);
            cp_commit();
            cp_wait1();
        } else {
            cp_wait0();
        }
        __syncthreads();
        compute_chunk2(sbase + (c & 1) * BUF2, wm, wn, lane, acc);
        __syncthreads();
    }
}

// ---------------------------------------------------------------------------
// cvt: fp32 -> (hi, lo) bf16 split
// ---------------------------------------------------------------------------
__global__ void cvt_kernel(const float* __restrict__ src,
                           __nv_bfloat16* __restrict__ hi,
                           __nv_bfloat16* __restrict__ lo, int n4) {
    int i = blockIdx.x * blockDim.x + threadIdx.x;
    if (i >= n4) return;
    float4 v = ((const float4*)src)[i];
    __nv_bfloat16 h0 = __float2bfloat16(v.x), h1 = __float2bfloat16(v.y);
    __nv_bfloat16 h2 = __float2bfloat16(v.z), h3 = __float2bfloat16(v.w);
    __nv_bfloat16 l0 = __float2bfloat16(v.x - __bfloat162float(h0));
    __nv_bfloat16 l1 = __float2bfloat16(v.y - __bfloat162float(h1));
    __nv_bfloat16 l2 = __float2bfloat16(v.z - __bfloat162float(h2));
    __nv_bfloat16 l3 = __float2bfloat16(v.w - __bfloat162float(h3));
    ((__nv_bfloat162*)hi)[2 * i]     = __halves2bfloat162(h0, h1);
    ((__nv_bfloat162*)hi)[2 * i + 1] = __halves2bfloat162(h2, h3);
    ((__nv_bfloat162*)lo)[2 * i]     = __halves2bfloat162(l0, l1);
    ((__nv_bfloat162*)lo)[2 * i + 1] = __halves2bfloat162(l2, l3);
}

// ---------------------------------------------------------------------------
// U1[b,s,r] = x[b,s,:] . x[b, 2+2r, :]  (fp32 exact); 1 warp/(b,s)
// ---------------------------------------------------------------------------
__global__ void u1_kernel(const float* __restrict__ x) {
    int gw = (blockIdx.x * blockDim.x + threadIdx.x) >> 5;
    int lane = threadIdx.x & 31;
    if (gw >= MM) return;
    int b = gw >> 11;
    const float4* xr = (const float4*)(x + (size_t)gw * Dd);
    const float4* o0 = (const float4*)(x + ((size_t)b * Ss + 2) * Dd);
    const float4* o1 = (const float4*)(x + ((size_t)b * Ss + 4) * Dd);
    const float4* o2 = (const float4*)(x + ((size_t)b * Ss + 6) * Dd);
    const float4* o3 = (const float4*)(x + ((size_t)b * Ss + 8) * Dd);
    float a0 = 0.f, a1 = 0.f, a2 = 0.f, a3 = 0.f;
    for (int j = lane; j < Dd / 4; j += 32) {
        float4 xv = xr[j];
        float4 v;
        v = o0[j]; a0 += xv.x * v.x + xv.y * v.y + xv.z * v.z + xv.w * v.w;
        v = o1[j]; a1 += xv.x * v.x + xv.y * v.y + xv.z * v.z + xv.w * v.w;
        v = o2[j]; a2 += xv.x * v.x + xv.y * v.y + xv.z * v.z + xv.w * v.w;
        v = o3[j]; a3 += xv.x * v.x + xv.y * v.y + xv.z * v.z + xv.w * v.w;
    }
    #pragma unroll
    for (int off = 16; off; off >>= 1) {
        a0 += __shfl_xor_sync(0xFFFFFFFFu, a0, off);
        a1 += __shfl_xor_sync(0xFFFFFFFFu, a1, off);
        a2 += __shfl_xor_sync(0xFFFFFFFFu, a2, off);
        a3 += __shfl_xor_sync(0xFFFFFFFFu, a3, off);
    }
    if (lane == 0) {
        g_U1[gw * 4 + 0] = a0;
        g_U1[gw * 4 + 1] = a1;
        g_U1[gw * 4 + 2] = a2;
        g_U1[gw * 4 + 3] = a3;
    }
}

// ---------------------------------------------------------------------------
// V[b,s,r,k] = sum_j h[b,s,k*1024+j] * x[b,10+2r,j]; h = hhi + hlo
// ---------------------------------------------------------------------------
__global__ void v_kernel(const float* __restrict__ x) {
    int gw = (blockIdx.x * blockDim.x + threadIdx.x) >> 5;
    int lane = threadIdx.x & 31;
    if (gw >= MM) return;
    int b = gw >> 11;
    const float2* od[4];
    #pragma unroll
    for (int r = 0; r < 4; r++)
        od[r] = (const float2*)(x + ((size_t)b * Ss + 10 + 2 * r) * Dd);
    float acc[16];
    #pragma unroll
    for (int i = 0; i < 16; i++) acc[i] = 0.f;
    #pragma unroll
    for (int k = 0; k < 4; k++) {
        const __nv_bfloat162* hh = (const __nv_bfloat162*)(g_hhi + (size_t)gw * Hh + k * 1024);
        const __nv_bfloat162* hl = (const __nv_bfloat162*)(g_hlo + (size_t)gw * Hh + k * 1024);
        for (int j = lane; j < 512; j += 32) {
            float2 a = __bfloat1622float2(hh[j]);
            float2 c = __bfloat1622float2(hl[j]);
            float hx = a.x + c.x, hy = a.y + c.y;
            #pragma unroll
            for (int r = 0; r < 4; r++) {
                float2 ov = od[r][j];
                acc[r * 4 + k] += hx * ov.x + hy * ov.y;
            }
        }
    }
    #pragma unroll
    for (int i = 0; i < 16; i++) {
        #pragma unroll
        for (int off = 16; off; off >>= 1)
            acc[i] += __shfl_xor_sync(0xFFFFFFFFu, acc[i], off);
    }
    if (lane == 0) {
        #pragma unroll
        for (int i = 0; i < 16; i++) g_V[gw * 16 + i] = acc[i];
    }
}

// ---------------------------------------------------------------------------
// GEMM1: h = gelu(x@W1^T + scale*lora1 + b1) -> split-bf16 g_hhi/g_hlo
// ---------------------------------------------------------------------------
__global__ __launch_bounds__(256, 2)
void gemm1_mma(const float* __restrict__ x, const float* __restrict__ b1,
               const float* __restrict__ scale_p) {
    int m0 = blockIdx.y * 128, n0 = blockIdx.x * 128;
    float acc[4][4][4];
    gemm_mma<Dd>(g_xhi, g_xlo, g_w1hi, g_w1lo, m0, n0, acc);

    int lane = threadIdx.x & 31, wid = threadIdx.x >> 5;
    int wm = wid >> 2, wn = wid & 3;
    float sc = *scale_p;
    int r = n0 >> 10;
    #pragma unroll
    for (int mi = 0; mi < 4; mi++) {
        #pragma unroll
        for (int half = 0; half < 2; half++) {
            int m = m0 + wm * 64 + mi * 16 + (lane >> 2) + half * 8;
            int b = m >> 11;
            float u = sc * g_U1[m * 4 + r];
            const float* ev = x + ((size_t)b * Ss + 1 + 2 * r) * Dd;
            #pragma unroll
            for (int ni = 0; ni < 4; ni++) {
                int n = n0 + wn * 32 + ni * 8 + 2 * (lane & 3);
                int nc = n & 1023;
                float c0 = acc[mi][ni][half * 2 + 0] + u * ev[nc]     + b1[n];
                float c1 = acc[mi][ni][half * 2 + 1] + u * ev[nc + 1] + b1[n + 1];
                float gg0 = gelu_exact(c0), gg1 = gelu_exact(c1);
                __nv_bfloat16 h0 = __float2bfloat16(gg0);
                __nv_bfloat16 h1 = __float2bfloat16(gg1);
                __nv_bfloat16 l0 = __float2bfloat16(gg0 - __bfloat162float(h0));
                __nv_bfloat16 l1 = __float2bfloat16(gg1 - __bfloat162float(h1));
                *(__nv_bfloat162*)(g_hhi + (size_t)m * Hh + n) = __halves2bfloat162(h0, h1);
                *(__nv_bfloat162*)(g_hlo + (size_t)m * Hh + n) = __halves2bfloat162(l0, l1);
            }
        }
    }
}

// ---------------------------------------------------------------------------
// GEMM2: out = h@W2^T + scale*lora2 + b2  (fp32 out); BM=64 tiles
// ---------------------------------------------------------------------------
__global__ __launch_bounds__(256, 2)
void gemm2_mma(const float* __restrict__ x, const float* __restrict__ b2,
               const float* __restrict__ scale_p, float* __restrict__ out) {
    int m0 = blockIdx.y * 64, n0 = blockIdx.x * 128;
    float acc[2][4][4];
    gemm_mma2<Hh>(g_hhi, g_hlo, g_w2hi, g_w2lo, m0, n0, acc);

    int lane = threadIdx.x & 31, wid = threadIdx.x >> 5;
    int wm = wid >> 2, wn = wid & 3;
    float sc = *scale_p;
    int r = n0 >> 8;
    #pragma unroll
    for (int mi = 0; mi < 2; mi++) {
        #pragma unroll
        for (int half = 0; half < 2; half++) {
            int m = m0 + wm * 32 + mi * 16 + (lane >> 2) + half * 8;
            int b = m >> 11;
            float4 vv = *(const float4*)&g_V[m * 16 + r * 4];
            const float4* ev2 = (const float4*)(x + ((size_t)b * Ss + 9 + 2 * r) * Dd);
            #pragma unroll
            for (int ni = 0; ni < 4; ni++) {
                int n = n0 + wn * 32 + ni * 8 + 2 * (lane & 3);
                float4 e0 = ev2[n & 255];
                float4 e1 = ev2[(n + 1) & 255];
                float lora0 = vv.x * e0.x + vv.y * e0.y + vv.z * e0.z + vv.w * e0.w;
                float lora1 = vv.x * e1.x + vv.y * e1.y + vv.z * e1.z + vv.w * e1.w;
                float2 o;
                o.x = acc[mi][ni][half * 2 + 0] + sc * lora0 + b2[n];
                o.y = acc[mi][ni][half * 2 + 1] + sc * lora1 + b2[n + 1];
                *(float2*)(out + (size_t)m * Dd + n) = o;
            }
        }
    }
}

// ---------------------------------------------------------------------------
extern "C" void kernel_launch(void* const* d_in, const int* in_sizes, int n_in,
                              void* d_out, int out_size) {
    const float* x     = (const float*)d_in[0];
    const float* W1    = (const float*)d_in[1];
    const float* b1    = (const float*)d_in[2];
    const float* W2    = (const float*)d_in[3];
    const float* b2    = (const float*)d_in[4];
    const float* scale = (const float*)d_in[5];
    float* out = (float*)d_out;

    cudaFuncSetAttribute(gemm1_mma, cudaFuncAttributeMaxDynamicSharedMemorySize, SMEM_TOTAL);
    cudaFuncSetAttribute(gemm2_mma, cudaFuncAttributeMaxDynamicSharedMemorySize, SMEM2);

    __nv_bfloat16 *xhi, *xlo, *w1hi, *w1lo, *w2hi, *w2lo;
    cudaGetSymbolAddress((void**)&xhi, g_xhi);
    cudaGetSymbolAddress((void**)&xlo, g_xlo);
    cudaGetSymbolAddress((void**)&w1hi, g_w1hi);
    cudaGetSymbolAddress((void**)&w1lo, g_w1lo);
    cudaGetSymbolAddress((void**)&w2hi, g_w2hi);
    cudaGetSymbolAddress((void**)&w2lo, g_w2lo);

    u1_kernel<<<MM / 8, 256>>>(x);

    cvt_kernel<<<(MM * Dd / 4 + 255) / 256, 256>>>(x, xhi, xlo, MM * Dd / 4);
    cvt_kernel<<<(Hh * Dd / 4 + 255) / 256, 256>>>(W1, w1hi, w1lo, Hh * Dd / 4);
    cvt_kernel<<<(Dd * Hh / 4 + 255) / 256, 256>>>(W2, w2hi, w2lo, Dd * Hh / 4);

    dim3 g1(Hh / 128, MM / 128);   // (32, 64)
    gemm1_mma<<<g1, 256, SMEM_TOTAL>>>(x, b1, scale);

    v_kernel<<<MM / 8, 256>>>(x);

    dim3 g2(Dd / 128, MM / 64);    // (8, 128) = 1024 CTAs
    gemm2_mma<<<g2, 256, SMEM2>>>(x, b2, scale, out);
}

// round 10
// speedup vs baseline: 1.4835x; 1.3113x over previous
#include <cuda_runtime.h>
#include <cuda_bf16.h>
#include <math.h>
#include <stdint.h>

// Problem constants
#define Bb 4
#define Ss 2048
#define Dd 1024
#define Hh 4096
#define MM (Bb * Ss)   // 8192

// ---------------------------------------------------------------------------
// Device-global scratch (allocation-free rule). tf32-rounded fp32 copies.
// ---------------------------------------------------------------------------
__device__ float g_xt[(size_t)MM * Dd];    // x, tf32-rounded
__device__ float g_w1t[(size_t)Hh * Dd];   // W1, tf32-rounded
__device__ float g_w2t[(size_t)Dd * Hh];   // W2, tf32-rounded
__device__ float g_ht[(size_t)MM * Hh];    // h (post-GELU), tf32-rounded
__device__ float g_U1[MM * 4];
__device__ float g_V[MM * 16];

__device__ __forceinline__ float gelu_exact(float v) {
    return 0.5f * v * (1.0f + erff(v * 0.70710678118654752f));
}

__device__ __forceinline__ float tf32r(float f) {
    uint32_t r;
    asm("cvt.rna.tf32.f32 %0, %1;" : "=r"(r) : "f"(f));
    return __uint_as_float(r);
}

// ---------------------------------------------------------------------------
// tf32 mma / cp.async primitives (baseline sm_80+ PTX -> sm_103 OK)
// ---------------------------------------------------------------------------
__device__ __forceinline__ void mma_tf32(float* d, const uint32_t* a, const uint32_t* b) {
    asm volatile(
        "mma.sync.aligned.m16n8k8.row.col.f32.tf32.tf32.f32 "
        "{%0,%1,%2,%3}, {%4,%5,%6,%7}, {%8,%9}, {%0,%1,%2,%3};"
        : "+f"(d[0]), "+f"(d[1]), "+f"(d[2]), "+f"(d[3])
        : "r"(a[0]), "r"(a[1]), "r"(a[2]), "r"(a[3]), "r"(b[0]), "r"(b[1]));
}

__device__ __forceinline__ void cp16(uint32_t s, const void* g) {
    asm volatile("cp.async.cg.shared.global [%0], [%1], 16;" :: "r"(s), "l"(g));
}
__device__ __forceinline__ void cp_commit() {
    asm volatile("cp.async.commit_group;" ::: "memory");
}
__device__ __forceinline__ void cp_wait0() {
    asm volatile("cp.async.wait_group 0;" ::: "memory");
}
__device__ __forceinline__ void cp_wait1() {
    asm volatile("cp.async.wait_group 1;" ::: "memory");
}

__device__ __forceinline__ uint32_t smem_u32(const void* p) {
    uint32_t a;
    asm("{ .reg .u64 t; cvta.to.shared.u64 t, %1; cvt.u32.u64 %0, t; }"
        : "=r"(a) : "l"(p));
    return a;
}

// ---------------------------------------------------------------------------
// Tiling: 128x128 CTA tile, BK=32 fp32, double buffer (R6-proven schedule)
// ---------------------------------------------------------------------------
#define BK 32
#define TS4 36                        // floats per smem row (32 data + 4 pad)
#define TILE4 (128 * TS4 * 4)         // 18432 B per tile
#define BUF4 (2 * TILE4)              // A + B = 36864 B per stage
#define SMEM4 (2 * BUF4)              // 73728 B double-buffered

extern __shared__ char dsmem[];

// Issue cp.async for one BK=32 chunk: A+B fp32 tiles, 8 cp16 per thread.
__device__ __forceinline__ void issue_chunk4(
    uint32_t sbuf, const float* __restrict__ At, const float* __restrict__ Bt,
    int m0, int n0, int kc, int KDIM, int tid)
{
    #pragma unroll
    for (int i = 0; i < 4; i++) {
        int idx = tid + i * 256;          // 0..1023
        int row = idx >> 3, c = idx & 7;  // 128 rows x 8 16B-chunks
        uint32_t soff = (uint32_t)(row * (TS4 * 4) + c * 16);
        size_t ga = (size_t)(m0 + row) * KDIM + kc * BK + c * 4;
        size_t gb = (size_t)(n0 + row) * KDIM + kc * BK + c * 4;
        cp16(sbuf + soff, At + ga);
        cp16(sbuf + TILE4 + soff, Bt + gb);
    }
}

// One BK=32 chunk of 1xTF32 compute: FOUR k8-steps (32 K-cols; R9 bug was 2).
// Per step: 16 A-LDS + 8 B-LDS (all conflict-free: bank=(4g+t)%32) + 16 MMA.
__device__ __forceinline__ void compute_chunk4(const char* buf, int wm, int wn, int lane,
                                               float acc[4][4][4]) {
    const float* As = (const float*)buf;
    const float* Bs = (const float*)(buf + TILE4);
    int g = lane >> 2, t = lane & 3;
    #pragma unroll
    for (int ks = 0; ks < 4; ks++) {
        int kb = ks * 8;
        uint32_t a[4][4], bf[4][2];
        #pragma unroll
        for (int mi = 0; mi < 4; mi++) {
            int r0 = wm * 64 + mi * 16 + g;
            a[mi][0] = __float_as_uint(As[r0 * TS4 + kb + t]);
            a[mi][1] = __float_as_uint(As[(r0 + 8) * TS4 + kb + t]);
            a[mi][2] = __float_as_uint(As[r0 * TS4 + kb + 4 + t]);
            a[mi][3] = __float_as_uint(As[(r0 + 8) * TS4 + kb + 4 + t]);
        }
        #pragma unroll
        for (int ni = 0; ni < 4; ni++) {
            int nr = wn * 32 + ni * 8 + g;
            bf[ni][0] = __float_as_uint(Bs[nr * TS4 + kb + t]);
            bf[ni][1] = __float_as_uint(Bs[nr * TS4 + kb + 4 + t]);
        }
        #pragma unroll
        for (int mi = 0; mi < 4; mi++)
            #pragma unroll
            for (int ni = 0; ni < 4; ni++)
                mma_tf32(acc[mi][ni], a[mi], bf[ni]);
    }
}

template <int KDIM>
__device__ __forceinline__ void gemm_tf32(
    const float* __restrict__ At, const float* __restrict__ Bt,
    int m0, int n0, float acc[4][4][4])
{
    int tid = threadIdx.x;
    int lane = tid & 31, wid = tid >> 5;
    int wm = wid >> 2, wn = wid & 3;
    uint32_t sbase = smem_u32(dsmem);

    #pragma unroll
    for (int mi = 0; mi < 4; mi++)
        #pragma unroll
        for (int ni = 0; ni < 4; ni++)
            #pragma unroll
            for (int q = 0; q < 4; q++) acc[mi][ni][q] = 0.f;

    const int NC = KDIM / BK;
    issue_chunk4(sbase, At, Bt, m0, n0, 0, KDIM, tid);
    cp_commit();
    for (int c = 0; c < NC; c++) {
        if (c + 1 < NC) {
            issue_chunk4(sbase + ((c + 1) & 1) * BUF4, At, Bt, m0, n0, c + 1, KDIM, tid);
            cp_commit();
            cp_wait1();
        } else {
            cp_wait0();
        }
        __syncthreads();
        compute_chunk4(dsmem + (c & 1) * BUF4, wm, wn, lane, acc);
        __syncthreads();
    }
}

// ---------------------------------------------------------------------------
// cvt: fp32 -> tf32-rounded fp32 (round-to-nearest; REQUIRED for unbiased err)
// ---------------------------------------------------------------------------
__global__ void cvt_tf32_kernel(const float* __restrict__ src,
                                float* __restrict__ dst, int n4) {
    int i = blockIdx.x * blockDim.x + threadIdx.x;
    if (i >= n4) return;
    float4 v = ((const float4*)src)[i];
    float4 o;
    o.x = tf32r(v.x); o.y = tf32r(v.y); o.z = tf32r(v.z); o.w = tf32r(v.w);
    ((float4*)dst)[i] = o;
}

// ---------------------------------------------------------------------------
// U1[b,s,r] = x[b,s,:] . x[b, 2+2r, :]  (fp32 exact); 1 warp/(b,s)
// ---------------------------------------------------------------------------
__global__ void u1_kernel(const float* __restrict__ x) {
    int gw = (blockIdx.x * blockDim.x + threadIdx.x) >> 5;
    int lane = threadIdx.x & 31;
    if (gw >= MM) return;
    int b = gw >> 11;
    const float4* xr = (const float4*)(x + (size_t)gw * Dd);
    const float4* o0 = (const float4*)(x + ((size_t)b * Ss + 2) * Dd);
    const float4* o1 = (const float4*)(x + ((size_t)b * Ss + 4) * Dd);
    const float4* o2 = (const float4*)(x + ((size_t)b * Ss + 6) * Dd);
    const float4* o3 = (const float4*)(x + ((size_t)b * Ss + 8) * Dd);
    float a0 = 0.f, a1 = 0.f, a2 = 0.f, a3 = 0.f;
    for (int j = lane; j < Dd / 4; j += 32) {
        float4 xv = xr[j];
        float4 v;
        v = o0[j]; a0 += xv.x * v.x + xv.y * v.y + xv.z * v.z + xv.w * v.w;
        v = o1[j]; a1 += xv.x * v.x + xv.y * v.y + xv.z * v.z + xv.w * v.w;
        v = o2[j]; a2 += xv.x * v.x + xv.y * v.y + xv.z * v.z + xv.w * v.w;
        v = o3[j]; a3 += xv.x * v.x + xv.y * v.y + xv.z * v.z + xv.w * v.w;
    }
    #pragma unroll
    for (int off = 16; off; off >>= 1) {
        a0 += __shfl_xor_sync(0xFFFFFFFFu, a0, off);
        a1 += __shfl_xor_sync(0xFFFFFFFFu, a1, off);
        a2 += __shfl_xor_sync(0xFFFFFFFFu, a2, off);
        a3 += __shfl_xor_sync(0xFFFFFFFFu, a3, off);
    }
    if (lane == 0) {
        g_U1[gw * 4 + 0] = a0;
        g_U1[gw * 4 + 1] = a1;
        g_U1[gw * 4 + 2] = a2;
        g_U1[gw * 4 + 3] = a3;
    }
}

// ---------------------------------------------------------------------------
// V[b,s,r,k] = sum_j h[b,s,k*1024+j] * x[b,10+2r,j]; h = g_ht (fp32)
// ---------------------------------------------------------------------------
__global__ void v_kernel(const float* __restrict__ x) {
    int gw = (blockIdx.x * blockDim.x + threadIdx.x) >> 5;
    int lane = threadIdx.x & 31;
    if (gw >= MM) return;
    int b = gw >> 11;
    const float4* od[4];
    #pragma unroll
    for (int r = 0; r < 4; r++)
        od[r] = (const float4*)(x + ((size_t)b * Ss + 10 + 2 * r) * Dd);
    float acc[16];
    #pragma unroll
    for (int i = 0; i < 16; i++) acc[i] = 0.f;
    #pragma unroll
    for (int k = 0; k < 4; k++) {
        const float4* hr = (const float4*)(g_ht + (size_t)gw * Hh + k * 1024);
        for (int j = lane; j < 256; j += 32) {
            float4 hv = hr[j];
            #pragma unroll
            for (int r = 0; r < 4; r++) {
                float4 ov = od[r][j];
                acc[r * 4 + k] += hv.x * ov.x + hv.y * ov.y + hv.z * ov.z + hv.w * ov.w;
            }
        }
    }
    #pragma unroll
    for (int i = 0; i < 16; i++) {
        #pragma unroll
        for (int off = 16; off; off >>= 1)
            acc[i] += __shfl_xor_sync(0xFFFFFFFFu, acc[i], off);
    }
    if (lane == 0) {
        #pragma unroll
        for (int i = 0; i < 16; i++) g_V[gw * 16 + i] = acc[i];
    }
}

// ---------------------------------------------------------------------------
// GEMM1: h = gelu(x@W1^T + scale*lora1 + b1) -> tf32-rounded fp32 g_ht
// ---------------------------------------------------------------------------
__global__ __launch_bounds__(256, 2)
void gemm1_mma(const float* __restrict__ x, const float* __restrict__ b1,
               const float* __restrict__ scale_p) {
    int m0 = blockIdx.y * 128, n0 = blockIdx.x * 128;
    float acc[4][4][4];
    gemm_tf32<Dd>(g_xt, g_w1t, m0, n0, acc);

    int lane = threadIdx.x & 31, wid = threadIdx.x >> 5;
    int wm = wid >> 2, wn = wid & 3;
    float sc = *scale_p;
    int r = n0 >> 10;
    #pragma unroll
    for (int mi = 0; mi < 4; mi++) {
        #pragma unroll
        for (int half = 0; half < 2; half++) {
            int m = m0 + wm * 64 + mi * 16 + (lane >> 2) + half * 8;
            int b = m >> 11;
            float u = sc * g_U1[m * 4 + r];
            const float* ev = x + ((size_t)b * Ss + 1 + 2 * r) * Dd;
            #pragma unroll
            for (int ni = 0; ni < 4; ni++) {
                int n = n0 + wn * 32 + ni * 8 + 2 * (lane & 3);
                int nc = n & 1023;
                float c0 = acc[mi][ni][half * 2 + 0] + u * ev[nc]     + b1[n];
                float c1 = acc[mi][ni][half * 2 + 1] + u * ev[nc + 1] + b1[n + 1];
                float2 o;
                o.x = tf32r(gelu_exact(c0));
                o.y = tf32r(gelu_exact(c1));
                *(float2*)(g_ht + (size_t)m * Hh + n) = o;
            }
        }
    }
}

// ---------------------------------------------------------------------------
// GEMM2: out = h@W2^T + scale*lora2 + b2  (fp32 out)
// ---------------------------------------------------------------------------
__global__ __launch_bounds__(256, 2)
void gemm2_mma(const float* __restrict__ x, const float* __restrict__ b2,
               const float* __restrict__ scale_p, float* __restrict__ out) {
    int m0 = blockIdx.y * 128, n0 = blockIdx.x * 128;
    float acc[4][4][4];
    gemm_tf32<Hh>(g_ht, g_w2t, m0, n0, acc);

    int lane = threadIdx.x & 31, wid = threadIdx.x >> 5;
    int wm = wid >> 2, wn = wid & 3;
    float sc = *scale_p;
    int r = n0 >> 8;
    #pragma unroll
    for (int mi = 0; mi < 4; mi++) {
        #pragma unroll
        for (int half = 0; half < 2; half++) {
            int m = m0 + wm * 64 + mi * 16 + (lane >> 2) + half * 8;
            int b = m >> 11;
            float4 vv = *(const float4*)&g_V[m * 16 + r * 4];
            const float4* ev2 = (const float4*)(x + ((size_t)b * Ss + 9 + 2 * r) * Dd);
            #pragma unroll
            for (int ni = 0; ni < 4; ni++) {
                int n = n0 + wn * 32 + ni * 8 + 2 * (lane & 3);
                float4 e0 = ev2[n & 255];
                float4 e1 = ev2[(n + 1) & 255];
                float lora0 = vv.x * e0.x + vv.y * e0.y + vv.z * e0.z + vv.w * e0.w;
                float lora1 = vv.x * e1.x + vv.y * e1.y + vv.z * e1.z + vv.w * e1.w;
                float2 o;
                o.x = acc[mi][ni][half * 2 + 0] + sc * lora0 + b2[n];
                o.y = acc[mi][ni][half * 2 + 1] + sc * lora1 + b2[n + 1];
                *(float2*)(out + (size_t)m * Dd + n) = o;
            }
        }
    }
}

// ---------------------------------------------------------------------------
extern "C" void kernel_launch(void* const* d_in, const int* in_sizes, int n_in,
                              void* d_out, int out_size) {
    const float* x     = (const float*)d_in[0];
    const float* W1    = (const float*)d_in[1];
    const float* b1    = (const float*)d_in[2];
    const float* W2    = (const float*)d_in[3];
    const float* b2    = (const float*)d_in[4];
    const float* scale = (const float*)d_in[5];
    float* out = (float*)d_out;

    cudaFuncSetAttribute(gemm1_mma, cudaFuncAttributeMaxDynamicSharedMemorySize, SMEM4);
    cudaFuncSetAttribute(gemm2_mma, cudaFuncAttributeMaxDynamicSharedMemorySize, SMEM4);

    float *xt, *w1t, *w2t;
    cudaGetSymbolAddress((void**)&xt, g_xt);
    cudaGetSymbolAddress((void**)&w1t, g_w1t);
    cudaGetSymbolAddress((void**)&w2t, g_w2t);

    u1_kernel<<<MM / 8, 256>>>(x);

    cvt_tf32_kernel<<<(MM * Dd / 4 + 255) / 256, 256>>>(x, xt, MM * Dd / 4);
    cvt_tf32_kernel<<<(Hh * Dd / 4 + 255) / 256, 256>>>(W1, w1t, Hh * Dd / 4);
    cvt_tf32_kernel<<<(Dd * Hh / 4 + 255) / 256, 256>>>(W2, w2t, Dd * Hh / 4);

    dim3 g1(Hh / 128, MM / 128);   // (32, 64)
    gemm1_mma<<<g1, 256, SMEM4>>>(x, b1, scale);

    v_kernel<<<MM / 8, 256>>>(x);

    dim3 g2(Dd / 128, MM / 128);   // (8, 64)
    gemm2_mma<<<g2, 256, SMEM4>>>(x, b2, scale, out);
}

// round 11
// speedup vs baseline: 1.5883x; 1.0706x over previous
#include <cuda_runtime.h>
#include <math.h>
#include <stdint.h>

// Problem constants
#define Bb 4
#define Ss 2048
#define Dd 1024
#define Hh 4096
#define MM (Bb * Ss)   // 8192

// ---------------------------------------------------------------------------
// Device-global scratch. All GEMM operands stored K-PERMUTED: within every
// 8-group of the contraction dim, storage order = [k0,k4,k1,k5,k2,k6,k3,k7]
// (pos 2t holds orig t, pos 2t+1 holds orig t+4). W1 additionally has its
// H-rows permuted the same way, so gemm1's output n-order == permuted H ==
// exactly what gemm2 needs as its K layout.
// ---------------------------------------------------------------------------
__device__ float g_xt[(size_t)MM * Dd];    // x, tf32-rounded, D k-perm
__device__ float g_w1t[(size_t)Hh * Dd];   // W1, tf32-rounded, D k-perm + H row-perm
__device__ float g_w2t[(size_t)Dd * Hh];   // W2, tf32-rounded, H k-perm
__device__ float g_ht[(size_t)MM * Hh];    // h (post-GELU), tf32-rounded, H perm
__device__ float g_U1[MM * 4];
__device__ float g_V[MM * 16];

__device__ __forceinline__ float gelu_exact(float v) {
    return 0.5f * v * (1.0f + erff(v * 0.70710678118654752f));
}

__device__ __forceinline__ float tf32r(float f) {
    uint32_t r;
    asm("cvt.rna.tf32.f32 %0, %1;" : "=r"(r) : "f"(f));
    return __uint_as_float(r);
}

// ---------------------------------------------------------------------------
// tf32 mma / cp.async primitives
// ---------------------------------------------------------------------------
__device__ __forceinline__ void mma_tf32(float* d, const uint32_t* a, const uint32_t* b) {
    asm volatile(
        "mma.sync.aligned.m16n8k8.row.col.f32.tf32.tf32.f32 "
        "{%0,%1,%2,%3}, {%4,%5,%6,%7}, {%8,%9}, {%0,%1,%2,%3};"
        : "+f"(d[0]), "+f"(d[1]), "+f"(d[2]), "+f"(d[3])
        : "r"(a[0]), "r"(a[1]), "r"(a[2]), "r"(a[3]), "r"(b[0]), "r"(b[1]));
}

__device__ __forceinline__ void cp16(uint32_t s, const void* g) {
    asm volatile("cp.async.cg.shared.global [%0], [%1], 16;" :: "r"(s), "l"(g));
}
__device__ __forceinline__ void cp_commit() {
    asm volatile("cp.async.commit_group;" ::: "memory");
}
__device__ __forceinline__ void cp_wait0() {
    asm volatile("cp.async.wait_group 0;" ::: "memory");
}
__device__ __forceinline__ void cp_wait1() {
    asm volatile("cp.async.wait_group 1;" ::: "memory");
}

__device__ __forceinline__ uint32_t smem_u32(const void* p) {
    uint32_t a;
    asm("{ .reg .u64 t; cvta.to.shared.u64 t, %1; cvt.u32.u64 %0, t; }"
        : "=r"(a) : "l"(p));
    return a;
}

// ---------------------------------------------------------------------------
// Tiling: 128x128 CTA tile, BK=32, double buffer. TS4=40 floats/row so that
// paired 64-bit fragment loads are conflict-free (bank = (8g+2t)%32).
// ---------------------------------------------------------------------------
#define BK 32
#define TS4 40                        // floats per smem row (32 data + 8 pad)
#define TILE4 (128 * TS4 * 4)         // 20480 B per tile
#define BUF4 (2 * TILE4)              // A + B = 40960 B per stage
#define SMEM4 (2 * BUF4)              // 81920 B double-buffered

extern __shared__ char dsmem[];

__device__ __forceinline__ void issue_chunk4(
    uint32_t sbuf, const float* __restrict__ At, const float* __restrict__ Bt,
    int m0, int n0, int kc, int KDIM, int tid)
{
    #pragma unroll
    for (int i = 0; i < 4; i++) {
        int idx = tid + i * 256;          // 0..1023
        int row = idx >> 3, c = idx & 7;  // 128 rows x 8 16B-chunks
        uint32_t soff = (uint32_t)(row * (TS4 * 4) + c * 16);
        size_t ga = (size_t)(m0 + row) * KDIM + kc * BK + c * 4;
        size_t gb = (size_t)(n0 + row) * KDIM + kc * BK + c * 4;
        cp16(sbuf + soff, At + ga);
        cp16(sbuf + TILE4 + soff, Bt + gb);
    }
}

// One BK=32 chunk: 4 k8-steps. K-perm storage -> each fragment pair is one
// 64-bit LDS: per step 8 A-LDS.64 + 4 B-LDS.64 + 16 MMA (was 24 LDS.32).
// Slot mapping preserved: pos 2t = MMA k-slot t, pos 2t+1 = slot t+4.
__device__ __forceinline__ void compute_chunk4(const char* buf, int wm, int wn, int lane,
                                               float acc[4][4][4]) {
    const float2* As = (const float2*)buf;          // row stride TS4/2 = 20
    const float2* Bs = (const float2*)(buf + TILE4);
    int g = lane >> 2, t = lane & 3;
    #pragma unroll
    for (int ks = 0; ks < 4; ks++) {
        int kb2 = ks * 4 + t;                        // float2 index within row
        uint32_t a[4][4], bf[4][2];
        #pragma unroll
        for (int mi = 0; mi < 4; mi++) {
            int r0 = wm * 64 + mi * 16 + g;
            float2 p0 = As[r0 * 20 + kb2];
            float2 p1 = As[(r0 + 8) * 20 + kb2];
            a[mi][0] = __float_as_uint(p0.x);        // k-slot t,   row g
            a[mi][1] = __float_as_uint(p1.x);        // k-slot t,   row g+8
            a[mi][2] = __float_as_uint(p0.y);        // k-slot t+4, row g
            a[mi][3] = __float_as_uint(p1.y);        // k-slot t+4, row g+8
        }
        #pragma unroll
        for (int ni = 0; ni < 4; ni++) {
            int nr = wn * 32 + ni * 8 + g;
            float2 pb = Bs[nr * 20 + kb2];
            bf[ni][0] = __float_as_uint(pb.x);       // k-slot t
            bf[ni][1] = __float_as_uint(pb.y);       // k-slot t+4
        }
        #pragma unroll
        for (int mi = 0; mi < 4; mi++)
            #pragma unroll
            for (int ni = 0; ni < 4; ni++)
                mma_tf32(acc[mi][ni], a[mi], bf[ni]);
    }
}

template <int KDIM>
__device__ __forceinline__ void gemm_tf32(
    const float* __restrict__ At, const float* __restrict__ Bt,
    int m0, int n0, float acc[4][4][4])
{
    int tid = threadIdx.x;
    int lane = tid & 31, wid = tid >> 5;
    int wm = wid >> 2, wn = wid & 3;
    uint32_t sbase = smem_u32(dsmem);

    #pragma unroll
    for (int mi = 0; mi < 4; mi++)
        #pragma unroll
        for (int ni = 0; ni < 4; ni++)
            #pragma unroll
            for (int q = 0; q < 4; q++) acc[mi][ni][q] = 0.f;

    const int NC = KDIM / BK;
    issue_chunk4(sbase, At, Bt, m0, n0, 0, KDIM, tid);
    cp_commit();
    for (int c = 0; c < NC; c++) {
        if (c + 1 < NC) {
            issue_chunk4(sbase + ((c + 1) & 1) * BUF4, At, Bt, m0, n0, c + 1, KDIM, tid);
            cp_commit();
            cp_wait1();
        } else {
            cp_wait0();
        }
        __syncthreads();
        compute_chunk4(dsmem + (c & 1) * BUF4, wm, wn, lane, acc);
        __syncthreads();
    }
}

// ---------------------------------------------------------------------------
// cvt kernels: tf32-round + K-group permutation.
// Permuted 8-group from orig (v0 = k0..3, v1 = k4..7):
//   out0 = (v0.x, v1.x, v0.y, v1.y), out1 = (v0.z, v1.z, v0.w, v1.w)
// ---------------------------------------------------------------------------
__device__ __forceinline__ void perm_pair(float4 v0, float4 v1, float4& o0, float4& o1) {
    o0.x = tf32r(v0.x); o0.y = tf32r(v1.x); o0.z = tf32r(v0.y); o0.w = tf32r(v1.y);
    o1.x = tf32r(v0.z); o1.y = tf32r(v1.z); o1.z = tf32r(v0.w); o1.w = tf32r(v1.w);
}

__global__ void cvt_kperm_kernel(const float* __restrict__ src,
                                 float* __restrict__ dst, int n8) {
    int i = blockIdx.x * blockDim.x + threadIdx.x;   // 8-group index
    if (i >= n8) return;
    float4 v0 = ((const float4*)src)[2 * i];
    float4 v1 = ((const float4*)src)[2 * i + 1];
    float4 o0, o1;
    perm_pair(v0, v1, o0, o1);
    ((float4*)dst)[2 * i]     = o0;
    ((float4*)dst)[2 * i + 1] = o1;
}

// W1: K-perm along D (cols) AND row-perm along H (so gemm1 output n-order is
// the permuted H order gemm2 expects). orig row o -> dst row:
// (o&~7) + ((o&7)<4 ? 2*(o&7) : 2*((o&7)-4)+1)
__global__ void cvt_w1_kernel(const float* __restrict__ src,
                              float* __restrict__ dst) {
    int i = blockIdx.x * blockDim.x + threadIdx.x;   // over Hh * (Dd/8)
    if (i >= Hh * (Dd / 8)) return;
    int row = i / (Dd / 8), c8 = i % (Dd / 8);
    int r7 = row & 7;
    int drow = (row & ~7) + ((r7 < 4) ? 2 * r7 : 2 * (r7 - 4) + 1);
    const float4* s = (const float4*)(src + (size_t)row * Dd) + 2 * c8;
    float4 o0, o1;
    perm_pair(s[0], s[1], o0, o1);
    float4* d = (float4*)(dst + (size_t)drow * Dd) + 2 * c8;
    d[0] = o0; d[1] = o1;
}

// ---------------------------------------------------------------------------
// U1[b,s,r] = x[b,s,:] . x[b, 2+2r, :]  (fp32 exact, orig x); 1 warp/(b,s)
// ---------------------------------------------------------------------------
__global__ void u1_kernel(const float* __restrict__ x) {
    int gw = (blockIdx.x * blockDim.x + threadIdx.x) >> 5;
    int lane = threadIdx.x & 31;
    if (gw >= MM) return;
    int b = gw >> 11;
    const float4* xr = (const float4*)(x + (size_t)gw * Dd);
    const float4* o0 = (const float4*)(x + ((size_t)b * Ss + 2) * Dd);
    const float4* o1 = (const float4*)(x + ((size_t)b * Ss + 4) * Dd);
    const float4* o2 = (const float4*)(x + ((size_t)b * Ss + 6) * Dd);
    const float4* o3 = (const float4*)(x + ((size_t)b * Ss + 8) * Dd);
    float a0 = 0.f, a1 = 0.f, a2 = 0.f, a3 = 0.f;
    for (int j = lane; j < Dd / 4; j += 32) {
        float4 xv = xr[j];
        float4 v;
        v = o0[j]; a0 += xv.x * v.x + xv.y * v.y + xv.z * v.z + xv.w * v.w;
        v = o1[j]; a1 += xv.x * v.x + xv.y * v.y + xv.z * v.z + xv.w * v.w;
        v = o2[j]; a2 += xv.x * v.x + xv.y * v.y + xv.z * v.z + xv.w * v.w;
        v = o3[j]; a3 += xv.x * v.x + xv.y * v.y + xv.z * v.z + xv.w * v.w;
    }
    #pragma unroll
    for (int off = 16; off; off >>= 1) {
        a0 += __shfl_xor_sync(0xFFFFFFFFu, a0, off);
        a1 += __shfl_xor_sync(0xFFFFFFFFu, a1, off);
        a2 += __shfl_xor_sync(0xFFFFFFFFu, a2, off);
        a3 += __shfl_xor_sync(0xFFFFFFFFu, a3, off);
    }
    if (lane == 0) {
        g_U1[gw * 4 + 0] = a0;
        g_U1[gw * 4 + 1] = a1;
        g_U1[gw * 4 + 2] = a2;
        g_U1[gw * 4 + 3] = a3;
    }
}

// ---------------------------------------------------------------------------
// V[b,s,r,k] = sum_j h[k*1024+j] * x_od[j].  g_ht is H-permuted: stored
// float4 pair (h4a, h4b) of 8-group g8 holds orig offsets {0,4,1,5} / {2,6,3,7}
// -> pair with x components (xlo.x,xhi.x,xlo.y,xhi.y) / (xlo.z,xhi.z,xlo.w,xhi.w)
// ---------------------------------------------------------------------------
__global__ void v_kernel(const float* __restrict__ x) {
    int gw = (blockIdx.x * blockDim.x + threadIdx.x) >> 5;
    int lane = threadIdx.x & 31;
    if (gw >= MM) return;
    int b = gw >> 11;
    const float4* od[4];
    #pragma unroll
    for (int r = 0; r < 4; r++)
        od[r] = (const float4*)(x + ((size_t)b * Ss + 10 + 2 * r) * Dd);
    float acc[16];
    #pragma unroll
    for (int i = 0; i < 16; i++) acc[i] = 0.f;
    #pragma unroll
    for (int k = 0; k < 4; k++) {
        const float4* hr = (const float4*)(g_ht + (size_t)gw * Hh + k * 1024);
        for (int j8 = lane; j8 < 128; j8 += 32) {
            float4 ha = hr[2 * j8];
            float4 hb = hr[2 * j8 + 1];
            #pragma unroll
            for (int r = 0; r < 4; r++) {
                float4 xlo = od[r][2 * j8];
                float4 xhi = od[r][2 * j8 + 1];
                acc[r * 4 + k] += ha.x * xlo.x + ha.y * xhi.x + ha.z * xlo.y + ha.w * xhi.y
                                + hb.x * xlo.z + hb.y * xhi.z + hb.z * xlo.w + hb.w * xhi.w;
            }
        }
    }
    #pragma unroll
    for (int i = 0; i < 16; i++) {
        #pragma unroll
        for (int off = 16; off; off >>= 1)
            acc[i] += __shfl_xor_sync(0xFFFFFFFFu, acc[i], off);
    }
    if (lane == 0) {
        #pragma unroll
        for (int i = 0; i < 16; i++) g_V[gw * 16 + i] = acc[i];
    }
}

// ---------------------------------------------------------------------------
// GEMM1: h = gelu(x@W1^T + scale*lora1 + b1) -> g_ht (H-permuted order).
// W1 rows were pre-permuted, so acc col pair (2t, 2t+1) = orig n (t, t+4).
// ---------------------------------------------------------------------------
__global__ __launch_bounds__(256, 2)
void gemm1_mma(const float* __restrict__ x, const float* __restrict__ b1,
               const float* __restrict__ scale_p) {
    int m0 = blockIdx.y * 128, n0 = blockIdx.x * 128;
    float acc[4][4][4];
    gemm_tf32<Dd>(g_xt, g_w1t, m0, n0, acc);

    int lane = threadIdx.x & 31, wid = threadIdx.x >> 5;
    int wm = wid >> 2, wn = wid & 3;
    int t = lane & 3;
    float sc = *scale_p;
    int r = n0 >> 10;
    #pragma unroll
    for (int mi = 0; mi < 4; mi++) {
        #pragma unroll
        for (int half = 0; half < 2; half++) {
            int m = m0 + wm * 64 + mi * 16 + (lane >> 2) + half * 8;
            int b = m >> 11;
            float u = sc * g_U1[m * 4 + r];
            const float* ev = x + ((size_t)b * Ss + 1 + 2 * r) * Dd;
            #pragma unroll
            for (int ni = 0; ni < 4; ni++) {
                int g8 = n0 + wn * 32 + ni * 8;          // 8-group base (orig==stored)
                int no0 = g8 + t;                        // orig n of acc[..][0]
                int no1 = g8 + t + 4;                    // orig n of acc[..][1]
                float c0 = acc[mi][ni][half * 2 + 0] + u * ev[no0 & 1023] + b1[no0];
                float c1 = acc[mi][ni][half * 2 + 1] + u * ev[no1 & 1023] + b1[no1];
                float2 o;
                o.x = tf32r(gelu_exact(c0));
                o.y = tf32r(gelu_exact(c1));
                *(float2*)(g_ht + (size_t)m * Hh + g8 + 2 * t) = o;   // stored pos
            }
        }
    }
}

// ---------------------------------------------------------------------------
// GEMM2: out = h@W2^T + scale*lora2 + b2  (fp32 out, natural D order)
// ---------------------------------------------------------------------------
__global__ __launch_bounds__(256, 2)
void gemm2_mma(const float* __restrict__ x, const float* __restrict__ b2,
               const float* __restrict__ scale_p, float* __restrict__ out) {
    int m0 = blockIdx.y * 128, n0 = blockIdx.x * 128;
    float acc[4][4][4];
    gemm_tf32<Hh>(g_ht, g_w2t, m0, n0, acc);

    int lane = threadIdx.x & 31, wid = threadIdx.x >> 5;
    int wm = wid >> 2, wn = wid & 3;
    float sc = *scale_p;
    int r = n0 >> 8;
    #pragma unroll
    for (int mi = 0; mi < 4; mi++) {
        #pragma unroll
        for (int half = 0; half < 2; half++) {
            int m = m0 + wm * 64 + mi * 16 + (lane >> 2) + half * 8;
            int b = m >> 11;
            float4 vv = *(const float4*)&g_V[m * 16 + r * 4];
            const float4* ev2 = (const float4*)(x + ((size_t)b * Ss + 9 + 2 * r) * Dd);
            #pragma unroll
            for (int ni = 0; ni < 4; ni++) {
                int n = n0 + wn * 32 + ni * 8 + 2 * (lane & 3);
                float4 e0 = ev2[n & 255];
                float4 e1 = ev2[(n + 1) & 255];
                float lora0 = vv.x * e0.x + vv.y * e0.y + vv.z * e0.z + vv.w * e0.w;
                float lora1 = vv.x * e1.x + vv.y * e1.y + vv.z * e1.z + vv.w * e1.w;
                float2 o;
                o.x = acc[mi][ni][half * 2 + 0] + sc * lora0 + b2[n];
                o.y = acc[mi][ni][half * 2 + 1] + sc * lora1 + b2[n + 1];
                *(float2*)(out + (size_t)m * Dd + n) = o;
            }
        }
    }
}

// ---------------------------------------------------------------------------
extern "C" void kernel_launch(void* const* d_in, const int* in_sizes, int n_in,
                              void* d_out, int out_size) {
    const float* x     = (const float*)d_in[0];
    const float* W1    = (const float*)d_in[1];
    const float* b1    = (const float*)d_in[2];
    const float* W2    = (const float*)d_in[3];
    const float* b2    = (const float*)d_in[4];
    const float* scale = (const float*)d_in[5];
    float* out = (float*)d_out;

    cudaFuncSetAttribute(gemm1_mma, cudaFuncAttributeMaxDynamicSharedMemorySize, SMEM4);
    cudaFuncSetAttribute(gemm2_mma, cudaFuncAttributeMaxDynamicSharedMemorySize, SMEM4);

    float *xt, *w1t, *w2t;
    cudaGetSymbolAddress((void**)&xt, g_xt);
    cudaGetSymbolAddress((void**)&w1t, g_w1t);
    cudaGetSymbolAddress((void**)&w2t, g_w2t);

    u1_kernel<<<MM / 8, 256>>>(x);

    cvt_kperm_kernel<<<(MM * Dd / 8 + 255) / 256, 256>>>(x, xt, MM * Dd / 8);
    cvt_w1_kernel<<<(Hh * (Dd / 8) + 255) / 256, 256>>>(W1, w1t);
    cvt_kperm_kernel<<<(Dd * Hh / 8 + 255) / 256, 256>>>(W2, w2t, Dd * Hh / 8);

    dim3 g1(Hh / 128, MM / 128);   // (32, 64)
    gemm1_mma<<<g1, 256, SMEM4>>>(x, b1, scale);

    v_kernel<<<MM / 8, 256>>>(x);

    dim3 g2(Dd / 128, MM / 128);   // (8, 64)
    gemm2_mma<<<g2, 256, SMEM4>>>(x, b2, scale, out);
}

// round 12
// speedup vs baseline: 2.9191x; 1.8378x over previous
#include <cuda_runtime.h>
#include <cuda_fp16.h>
#include <math.h>
#include <stdint.h>

// Problem constants
#define Bb 4
#define Ss 2048
#define Dd 1024
#define Hh 4096
#define MM (Bb * Ss)   // 8192

// ---------------------------------------------------------------------------
// Device-global scratch (allocation-free rule). fp16 (rn-rounded) operands.
// ---------------------------------------------------------------------------
__device__ __half g_xh[(size_t)MM * Dd];
__device__ __half g_w1h[(size_t)Hh * Dd];
__device__ __half g_w2h[(size_t)Dd * Hh];
__device__ __half g_hh[(size_t)MM * Hh];   // post-GELU hidden, fp16
__device__ float g_U1[MM * 4];
__device__ float g_V[MM * 16];

__device__ __forceinline__ float gelu_exact(float v) {
    return 0.5f * v * (1.0f + erff(v * 0.70710678118654752f));
}

__device__ __forceinline__ uint32_t smem_u32(const void* p) {
    uint32_t a;
    asm("{ .reg .u64 t; cvta.to.shared.u64 t, %1; cvt.u32.u64 %0, t; }"
        : "=r"(a) : "l"(p));
    return a;
}

// ---------------------------------------------------------------------------
// fp16 mma / ldmatrix / cp.async primitives (sm_75+/80+ PTX -> sm_103 OK)
// ---------------------------------------------------------------------------
__device__ __forceinline__ void mma16816h(float* d, const uint32_t* a, const uint32_t* b) {
    asm volatile(
        "mma.sync.aligned.m16n8k16.row.col.f32.f16.f16.f32 "
        "{%0,%1,%2,%3}, {%4,%5,%6,%7}, {%8,%9}, {%0,%1,%2,%3};"
        : "+f"(d[0]), "+f"(d[1]), "+f"(d[2]), "+f"(d[3])
        : "r"(a[0]), "r"(a[1]), "r"(a[2]), "r"(a[3]), "r"(b[0]), "r"(b[1]));
}

__device__ __forceinline__ void ldm4(uint32_t* r, uint32_t addr) {
    asm volatile("ldmatrix.sync.aligned.m8n8.x4.shared.b16 {%0,%1,%2,%3}, [%4];"
                 : "=r"(r[0]), "=r"(r[1]), "=r"(r[2]), "=r"(r[3]) : "r"(addr));
}

__device__ __forceinline__ void cp16(uint32_t s, const void* g) {
    asm volatile("cp.async.cg.shared.global [%0], [%1], 16;" :: "r"(s), "l"(g));
}
__device__ __forceinline__ void cp_commit() {
    asm volatile("cp.async.commit_group;" ::: "memory");
}
__device__ __forceinline__ void cp_wait0() {
    asm volatile("cp.async.wait_group 0;" ::: "memory");
}
__device__ __forceinline__ void cp_wait1() {
    asm volatile("cp.async.wait_group 1;" ::: "memory");
}

// ---------------------------------------------------------------------------
// Tiling: 128x128 CTA tile, BK=64 fp16, double buffer (R6-proven schedule)
// ---------------------------------------------------------------------------
#define BK 64
#define TSTRIDE 144                   // 64 fp16 = 128 B data + 16 B pad
#define TILE_B (128 * TSTRIDE)        // 18432 B per tile
#define BUF_B (2 * TILE_B)            // A + B = 36864 B per stage
#define SMEM_TOTAL (2 * BUF_B)        // 73728 B double-buffered

extern __shared__ char dsmem[];

// Issue cp.async for one BK=64 chunk: 8 cp16 per thread (A + B tiles).
__device__ __forceinline__ void issue_chunk(
    uint32_t sbuf, const __half* __restrict__ Ah, const __half* __restrict__ Bh,
    int m0, int n0, int kc, int KDIM, int tid)
{
    #pragma unroll
    for (int i = 0; i < 4; i++) {
        int idx = tid + i * 256;          // 0..1023
        int row = idx >> 3, c = idx & 7;  // 128 rows x 8 16B-chunks
        uint32_t soff = (uint32_t)(row * TSTRIDE + c * 16);
        size_t ga = (size_t)(m0 + row) * KDIM + kc * BK + c * 8;
        size_t gb = (size_t)(n0 + row) * KDIM + kc * BK + c * 8;
        cp16(sbuf + soff, Ah + ga);
        cp16(sbuf + TILE_B + soff, Bh + gb);
    }
}

// Load 4 A fragments (64 rows x k16) from a tile.
__device__ __forceinline__ void lda(uint32_t a[4][4], uint32_t tile, int wm, int lane, int ks) {
    uint32_t koff = (uint32_t)(ks * 32 + (lane >> 4) * 16);
    #pragma unroll
    for (int mi = 0; mi < 4; mi++) {
        uint32_t addr = tile + (uint32_t)((wm * 64 + mi * 16 + (lane & 15)) * TSTRIDE) + koff;
        ldm4(a[mi], addr);
    }
}

// Load 4 B fragments (32 cols x k16) from a tile.
__device__ __forceinline__ void ldb(uint32_t b[4][2], uint32_t tile, int wn, int lane, int ks) {
    #pragma unroll
    for (int g = 0; g < 2; g++) {
        int nrow = wn * 32 + g * 16 + (lane & 7) + ((lane >> 4) & 1) * 8;
        uint32_t addr = tile + (uint32_t)(nrow * TSTRIDE) +
                        (uint32_t)(ks * 32 + ((lane >> 3) & 1) * 16);
        uint32_t r[4];
        ldm4(r, addr);
        b[2 * g][0] = r[0]; b[2 * g][1] = r[1];
        b[2 * g + 1][0] = r[2]; b[2 * g + 1][1] = r[3];
    }
}

// One BK=64 chunk, single-term fp16: 4 k16-steps, each 6 LDSM + 16 MMA.
__device__ __forceinline__ void compute_chunk(uint32_t sbuf, int wm, int wn, int lane,
                                              float acc[4][4][4]) {
    #pragma unroll
    for (int ks = 0; ks < 4; ks++) {
        uint32_t a[4][4], b[4][2];
        lda(a, sbuf, wm, lane, ks);
        ldb(b, sbuf + TILE_B, wn, lane, ks);
        #pragma unroll
        for (int mi = 0; mi < 4; mi++)
            #pragma unroll
            for (int ni = 0; ni < 4; ni++)
                mma16816h(acc[mi][ni], a[mi], b[ni]);
    }
}

template <int KDIM>
__device__ __forceinline__ void gemm_f16(
    const __half* __restrict__ Ah, const __half* __restrict__ Bh,
    int m0, int n0, float acc[4][4][4])
{
    int tid = threadIdx.x;
    int lane = tid & 31, wid = tid >> 5;
    int wm = wid >> 2, wn = wid & 3;
    uint32_t sbase = smem_u32(dsmem);

    #pragma unroll
    for (int mi = 0; mi < 4; mi++)
        #pragma unroll
        for (int ni = 0; ni < 4; ni++)
            #pragma unroll
            for (int q = 0; q < 4; q++) acc[mi][ni][q] = 0.f;

    const int NC = KDIM / BK;
    issue_chunk(sbase, Ah, Bh, m0, n0, 0, KDIM, tid);
    cp_commit();
    for (int c = 0; c < NC; c++) {
        if (c + 1 < NC) {
            issue_chunk(sbase + ((c + 1) & 1) * BUF_B, Ah, Bh, m0, n0, c + 1, KDIM, tid);
            cp_commit();
            cp_wait1();
        } else {
            cp_wait0();
        }
        __syncthreads();
        compute_chunk(sbase + (c & 1) * BUF_B, wm, wn, lane, acc);
        __syncthreads();
    }
}

// ---------------------------------------------------------------------------
// cvt: fp32 -> fp16 (round-to-nearest)
// ---------------------------------------------------------------------------
__global__ void cvt_f16_kernel(const float* __restrict__ src,
                               __half* __restrict__ dst, int n4) {
    int i = blockIdx.x * blockDim.x + threadIdx.x;
    if (i >= n4) return;
    float4 v = ((const float4*)src)[i];
    __half2* d = (__half2*)dst;
    d[2 * i]     = __floats2half2_rn(v.x, v.y);
    d[2 * i + 1] = __floats2half2_rn(v.z, v.w);
}

// ---------------------------------------------------------------------------
// U1[b,s,r] = x[b,s,:] . x[b, 2+2r, :]  (fp32 exact); 1 warp/(b,s)
// ---------------------------------------------------------------------------
__global__ void u1_kernel(const float* __restrict__ x) {
    int gw = (blockIdx.x * blockDim.x + threadIdx.x) >> 5;
    int lane = threadIdx.x & 31;
    if (gw >= MM) return;
    int b = gw >> 11;
    const float4* xr = (const float4*)(x + (size_t)gw * Dd);
    const float4* o0 = (const float4*)(x + ((size_t)b * Ss + 2) * Dd);
    const float4* o1 = (const float4*)(x + ((size_t)b * Ss + 4) * Dd);
    const float4* o2 = (const float4*)(x + ((size_t)b * Ss + 6) * Dd);
    const float4* o3 = (const float4*)(x + ((size_t)b * Ss + 8) * Dd);
    float a0 = 0.f, a1 = 0.f, a2 = 0.f, a3 = 0.f;
    for (int j = lane; j < Dd / 4; j += 32) {
        float4 xv = xr[j];
        float4 v;
        v = o0[j]; a0 += xv.x * v.x + xv.y * v.y + xv.z * v.z + xv.w * v.w;
        v = o1[j]; a1 += xv.x * v.x + xv.y * v.y + xv.z * v.z + xv.w * v.w;
        v = o2[j]; a2 += xv.x * v.x + xv.y * v.y + xv.z * v.z + xv.w * v.w;
        v = o3[j]; a3 += xv.x * v.x + xv.y * v.y + xv.z * v.z + xv.w * v.w;
    }
    #pragma unroll
    for (int off = 16; off; off >>= 1) {
        a0 += __shfl_xor_sync(0xFFFFFFFFu, a0, off);
        a1 += __shfl_xor_sync(0xFFFFFFFFu, a1, off);
        a2 += __shfl_xor_sync(0xFFFFFFFFu, a2, off);
        a3 += __shfl_xor_sync(0xFFFFFFFFu, a3, off);
    }
    if (lane == 0) {
        g_U1[gw * 4 + 0] = a0;
        g_U1[gw * 4 + 1] = a1;
        g_U1[gw * 4 + 2] = a2;
        g_U1[gw * 4 + 3] = a3;
    }
}

// ---------------------------------------------------------------------------
// V[b,s,r,k] = sum_j h[b,s,k*1024+j] * x[b,10+2r,j]; h from g_hh (fp16)
// ---------------------------------------------------------------------------
__global__ void v_kernel(const float* __restrict__ x) {
    int gw = (blockIdx.x * blockDim.x + threadIdx.x) >> 5;
    int lane = threadIdx.x & 31;
    if (gw >= MM) return;
    int b = gw >> 11;
    const float2* od[4];
    #pragma unroll
    for (int r = 0; r < 4; r++)
        od[r] = (const float2*)(x + ((size_t)b * Ss + 10 + 2 * r) * Dd);
    float acc[16];
    #pragma unroll
    for (int i = 0; i < 16; i++) acc[i] = 0.f;
    #pragma unroll
    for (int k = 0; k < 4; k++) {
        const __half2* hh = (const __half2*)(g_hh + (size_t)gw * Hh + k * 1024);
        for (int j = lane; j < 512; j += 32) {
            float2 hv = __half22float2(hh[j]);
            #pragma unroll
            for (int r = 0; r < 4; r++) {
                float2 ov = od[r][j];
                acc[r * 4 + k] += hv.x * ov.x + hv.y * ov.y;
            }
        }
    }
    #pragma unroll
    for (int i = 0; i < 16; i++) {
        #pragma unroll
        for (int off = 16; off; off >>= 1)
            acc[i] += __shfl_xor_sync(0xFFFFFFFFu, acc[i], off);
    }
    if (lane == 0) {
        #pragma unroll
        for (int i = 0; i < 16; i++) g_V[gw * 16 + i] = acc[i];
    }
}

// ---------------------------------------------------------------------------
// GEMM1: h = gelu(x@W1^T + scale*lora1 + b1) -> fp16 g_hh
// ---------------------------------------------------------------------------
__global__ __launch_bounds__(256, 2)
void gemm1_mma(const float* __restrict__ x, const float* __restrict__ b1,
               const float* __restrict__ scale_p) {
    int m0 = blockIdx.y * 128, n0 = blockIdx.x * 128;
    float acc[4][4][4];
    gemm_f16<Dd>(g_xh, g_w1h, m0, n0, acc);

    int lane = threadIdx.x & 31, wid = threadIdx.x >> 5;
    int wm = wid >> 2, wn = wid & 3;
    float sc = *scale_p;
    int r = n0 >> 10;
    #pragma unroll
    for (int mi = 0; mi < 4; mi++) {
        #pragma unroll
        for (int half = 0; half < 2; half++) {
            int m = m0 + wm * 64 + mi * 16 + (lane >> 2) + half * 8;
            int b = m >> 11;
            float u = sc * g_U1[m * 4 + r];
            const float* ev = x + ((size_t)b * Ss + 1 + 2 * r) * Dd;
            #pragma unroll
            for (int ni = 0; ni < 4; ni++) {
                int n = n0 + wn * 32 + ni * 8 + 2 * (lane & 3);
                int nc = n & 1023;
                float c0 = acc[mi][ni][half * 2 + 0] + u * ev[nc]     + b1[n];
                float c1 = acc[mi][ni][half * 2 + 1] + u * ev[nc + 1] + b1[n + 1];
                *(__half2*)(g_hh + (size_t)m * Hh + n) =
                    __floats2half2_rn(gelu_exact(c0), gelu_exact(c1));
            }
        }
    }
}

// ---------------------------------------------------------------------------
// GEMM2: out = h@W2^T + scale*lora2 + b2  (fp32 out)
// ---------------------------------------------------------------------------
__global__ __launch_bounds__(256, 2)
void gemm2_mma(const float* __restrict__ x, const float* __restrict__ b2,
               const float* __restrict__ scale_p, float* __restrict__ out) {
    int m0 = blockIdx.y * 128, n0 = blockIdx.x * 128;
    float acc[4][4][4];
    gemm_f16<Hh>(g_hh, g_w2h, m0, n0, acc);

    int lane = threadIdx.x & 31, wid = threadIdx.x >> 5;
    int wm = wid >> 2, wn = wid & 3;
    float sc = *scale_p;
    int r = n0 >> 8;
    #pragma unroll
    for (int mi = 0; mi < 4; mi++) {
        #pragma unroll
        for (int half = 0; half < 2; half++) {
            int m = m0 + wm * 64 + mi * 16 + (lane >> 2) + half * 8;
            int b = m >> 11;
            float4 vv = *(const float4*)&g_V[m * 16 + r * 4];
            const float4* ev2 = (const float4*)(x + ((size_t)b * Ss + 9 + 2 * r) * Dd);
            #pragma unroll
            for (int ni = 0; ni < 4; ni++) {
                int n = n0 + wn * 32 + ni * 8 + 2 * (lane & 3);
                float4 e0 = ev2[n & 255];
                float4 e1 = ev2[(n + 1) & 255];
                float lora0 = vv.x * e0.x + vv.y * e0.y + vv.z * e0.z + vv.w * e0.w;
                float lora1 = vv.x * e1.x + vv.y * e1.y + vv.z * e1.z + vv.w * e1.w;
                float2 o;
                o.x = acc[mi][ni][half * 2 + 0] + sc * lora0 + b2[n];
                o.y = acc[mi][ni][half * 2 + 1] + sc * lora1 + b2[n + 1];
                *(float2*)(out + (size_t)m * Dd + n) = o;
            }
        }
    }
}

// ---------------------------------------------------------------------------
extern "C" void kernel_launch(void* const* d_in, const int* in_sizes, int n_in,
                              void* d_out, int out_size) {
    const float* x     = (const float*)d_in[0];
    const float* W1    = (const float*)d_in[1];
    const float* b1    = (const float*)d_in[2];
    const float* W2    = (const float*)d_in[3];
    const float* b2    = (const float*)d_in[4];
    const float* scale = (const float*)d_in[5];
    float* out = (float*)d_out;

    cudaFuncSetAttribute(gemm1_mma, cudaFuncAttributeMaxDynamicSharedMemorySize, SMEM_TOTAL);
    cudaFuncSetAttribute(gemm2_mma, cudaFuncAttributeMaxDynamicSharedMemorySize, SMEM_TOTAL);

    __half *xh, *w1h, *w2h;
    cudaGetSymbolAddress((void**)&xh, g_xh);
    cudaGetSymbolAddress((void**)&w1h, g_w1h);
    cudaGetSymbolAddress((void**)&w2h, g_w2h);

    u1_kernel<<<MM / 8, 256>>>(x);

    cvt_f16_kernel<<<(MM * Dd / 4 + 255) / 256, 256>>>(x, xh, MM * Dd / 4);
    cvt_f16_kernel<<<(Hh * Dd / 4 + 255) / 256, 256>>>(W1, w1h, Hh * Dd / 4);
    cvt_f16_kernel<<<(Dd * Hh / 4 + 255) / 256, 256>>>(W2, w2h, Dd * Hh / 4);

    dim3 g1(Hh / 128, MM / 128);   // (32, 64)
    gemm1_mma<<<g1, 256, SMEM_TOTAL>>>(x, b1, scale);

    v_kernel<<<MM / 8, 256>>>(x);

    dim3 g2(Dd / 128, MM / 128);   // (8, 64)
    gemm2_mma<<<g2, 256, SMEM_TOTAL>>>(x, b2, scale, out);
}